// round 1
// baseline (speedup 1.0000x reference)
#include <cuda_runtime.h>
#include <math.h>

#define B_  2
#define S_  2048
#define D_  768
#define H_  12
#define HD_ 64
#define L_  4
#define FF_ 3072
#define NC_ 16
#define W_  128

// ---------------- scratch (static device arrays; no allocation) ----------------
__device__ float g_h [B_*S_*D_];
__device__ float g_q [B_*S_*D_];
__device__ float g_k [B_*S_*D_];
__device__ float g_v [B_*S_*D_];
__device__ float g_kg[B_*S_*D_];
__device__ float g_vg[B_*S_*D_];
__device__ float g_a [B_*S_*D_];
__device__ float g_t [B_*S_*D_];
__device__ float g_ff[B_*S_*FF_];
__device__ float g_qg[B_*D_];

// ---------------- helpers ----------------
__device__ __forceinline__ void block_reduce2(float a, float b, float* out2) {
    __shared__ float r1[8], r2[8];
    int lane = threadIdx.x & 31, wid = threadIdx.x >> 5;
#pragma unroll
    for (int o = 16; o > 0; o >>= 1) {
        a += __shfl_down_sync(0xffffffffu, a, o);
        b += __shfl_down_sync(0xffffffffu, b, o);
    }
    if (lane == 0) { r1[wid] = a; r2[wid] = b; }
    __syncthreads();
    if (wid == 0) {
        int nw = blockDim.x >> 5;
        a = (lane < nw) ? r1[lane] : 0.f;
        b = (lane < nw) ? r2[lane] : 0.f;
#pragma unroll
        for (int o = 4; o > 0; o >>= 1) {
            a += __shfl_down_sync(0xffffffffu, a, o);
            b += __shfl_down_sync(0xffffffffu, b, o);
        }
        if (lane == 0) { out2[0] = a; out2[1] = b; }
    }
    __syncthreads();
}

// ---------------- embedding + LN ----------------
__global__ void embed_ln_kernel(const int* __restrict__ src,
                                const float* __restrict__ etok,
                                const float* __restrict__ epos,
                                const float* __restrict__ gs,
                                const float* __restrict__ gb,
                                float* __restrict__ h) {
    int tok = blockIdx.x;              // 0..B*S-1
    int s   = tok & (S_ - 1);
    int tid = threadIdx.x;             // 256
    __shared__ float stat[2];
    size_t row = (size_t)src[tok] * D_;
    float vals[3]; float sum = 0.f, sq = 0.f;
#pragma unroll
    for (int i = 0; i < 3; i++) {
        int d = tid + i * 256;
        float v = etok[row + d] + epos[(size_t)s * D_ + d];
        vals[i] = v; sum += v; sq += v * v;
    }
    block_reduce2(sum, sq, stat);
    float mean = stat[0] * (1.f / D_);
    float var  = stat[1] * (1.f / D_) - mean * mean;
    float inv  = 1.f / sqrtf(var + 1e-5f);
#pragma unroll
    for (int i = 0; i < 3; i++) {
        int d = tid + i * 256;
        h[(size_t)tok * D_ + d] = (vals[i] - mean) * inv * gs[d] + gb[d];
    }
}

// ---------------- residual add + LN (in place on h) ----------------
__global__ void add_ln_kernel(float* __restrict__ h, const float* __restrict__ x,
                              const float* __restrict__ sc, const float* __restrict__ bi) {
    int tok = blockIdx.x;
    int tid = threadIdx.x;
    __shared__ float stat[2];
    float* hp = h + (size_t)tok * D_;
    const float* xp = x + (size_t)tok * D_;
    float vals[3]; float sum = 0.f, sq = 0.f;
#pragma unroll
    for (int i = 0; i < 3; i++) {
        int d = tid + i * 256;
        float v = hp[d] + xp[d];
        vals[i] = v; sum += v; sq += v * v;
    }
    block_reduce2(sum, sq, stat);
    float mean = stat[0] * (1.f / D_);
    float var  = stat[1] * (1.f / D_) - mean * mean;
    float inv  = 1.f / sqrtf(var + 1e-5f);
#pragma unroll
    for (int i = 0; i < 3; i++) {
        int d = tid + i * 256;
        hp[d] = (vals[i] - mean) * inv * sc[d] + bi[d];
    }
}

// ---------------- generic fp32 GEMM: C = act((A@B + bias) * alpha) ----------------
// A: MxK row-major, B: KxN row-major, bias: N. All dims divisible (M%64==N%64==K%16==0).
template <int ACT>
__global__ void gemm_kernel(const float* __restrict__ A, const float* __restrict__ Bm,
                            const float* __restrict__ bias, float* __restrict__ C,
                            int M, int N, int K, float alpha) {
    constexpr int BM = 64, BN = 64, BK = 16;
    __shared__ float As[BK][BM + 4];
    __shared__ float Bs[BK][BN];
    const int bm = blockIdx.y * BM, bn = blockIdx.x * BN;
    const int tid = threadIdx.x;          // 256
    const int tx = tid & 15, ty = tid >> 4;
    float acc[4][4] = {};
    for (int k0 = 0; k0 < K; k0 += BK) {
#pragma unroll
        for (int i = 0; i < 4; i++) {
            int idx = tid + i * 256;
            int r = idx >> 4, c = idx & 15;
            As[c][r] = A[(size_t)(bm + r) * K + k0 + c];
        }
#pragma unroll
        for (int i = 0; i < 4; i++) {
            int idx = tid + i * 256;
            int r = idx >> 6, c = idx & 63;
            Bs[r][c] = Bm[(size_t)(k0 + r) * N + bn + c];
        }
        __syncthreads();
#pragma unroll
        for (int kk = 0; kk < BK; kk++) {
            float4 a4 = *reinterpret_cast<const float4*>(&As[kk][ty * 4]);
            float4 b4 = *reinterpret_cast<const float4*>(&Bs[kk][tx * 4]);
            float av[4] = {a4.x, a4.y, a4.z, a4.w};
            float bv[4] = {b4.x, b4.y, b4.z, b4.w};
#pragma unroll
            for (int i = 0; i < 4; i++)
#pragma unroll
                for (int j = 0; j < 4; j++)
                    acc[i][j] = fmaf(av[i], bv[j], acc[i][j]);
        }
        __syncthreads();
    }
#pragma unroll
    for (int i = 0; i < 4; i++) {
        size_t row = (size_t)(bm + ty * 4 + i);
#pragma unroll
        for (int j = 0; j < 4; j++) {
            int col = bn + tx * 4 + j;
            float v = (acc[i][j] + bias[col]) * alpha;
            if (ACT == 1) v = 0.5f * v * (1.f + erff(v * 0.7071067811865476f));
            C[row * N + col] = v;
        }
    }
}

// ---------------- qg = (h[:,0,:] @ Wqg + bqg) / 8 ----------------
__global__ void qg_kernel(const float* __restrict__ h, const float* __restrict__ Wm,
                          const float* __restrict__ bias, float* __restrict__ qg) {
    int b = blockIdx.x;
    int j = blockIdx.y * 256 + threadIdx.x;
    __shared__ float hs[D_];
    for (int i = threadIdx.x; i < D_; i += 256) hs[i] = h[(size_t)b * S_ * D_ + i];
    __syncthreads();
    float s = 0.f;
    for (int kk = 0; kk < D_; kk++) s = fmaf(hs[kk], Wm[(size_t)kk * D_ + j], s);
    qg[b * D_ + j] = (s + bias[j]) * 0.125f;
}

// ---------------- sliding-window + global-key attention (flash-style) ----------------
__global__ void __launch_bounds__(128) attn_kernel(
    const float* __restrict__ q, const float* __restrict__ k, const float* __restrict__ v,
    const int* __restrict__ mask, float* __restrict__ out) {
    const int c = blockIdx.x, hh = blockIdx.y, b = blockIdx.z;
    const int qi = threadIdx.x;        // 0..127 = query within chunk
    __shared__ float ks[64][HD_];
    __shared__ float vs[64][HD_];
    __shared__ int vld[64];
    const size_t qoff = ((size_t)b * S_ + c * W_ + qi) * D_ + hh * HD_;
    float qr[HD_], acc[HD_];
#pragma unroll
    for (int d = 0; d < HD_; d += 4) {
        float4 t = *reinterpret_cast<const float4*>(q + qoff + d);
        qr[d] = t.x; qr[d + 1] = t.y; qr[d + 2] = t.z; qr[d + 3] = t.w;
    }
    float m = -1e30f, l = 0.f;
#pragma unroll
    for (int d = 0; d < HD_; d++) acc[d] = 0.f;

    // global key: position 0 of this batch (from sliding K/V projection)
    if (mask[(size_t)b * S_] != 0) {
        const size_t koff = ((size_t)b * S_) * D_ + hh * HD_;
        float s = 0.f;
#pragma unroll
        for (int d = 0; d < HD_; d++) s = fmaf(qr[d], k[koff + d], s);
        m = s; l = 1.f;
#pragma unroll
        for (int d = 0; d < HD_; d++) acc[d] = v[koff + d];
    }

    for (int t = 0; t < 6; t++) {
        __syncthreads();
        for (int e = qi; e < 64 * HD_; e += 128) {
            int r = e >> 6, d = e & 63;
            int p = c * W_ - W_ + t * 64 + r;
            float kv = 0.f, vv = 0.f;
            if (p >= 0 && p < S_) {
                size_t off = ((size_t)b * S_ + p) * D_ + hh * HD_ + d;
                kv = k[off]; vv = v[off];
            }
            ks[r][d] = kv; vs[r][d] = vv;
        }
        if (qi < 64) {
            int p = c * W_ - W_ + t * 64 + qi;
            vld[qi] = (p >= 0 && p < S_) ? (mask[(size_t)b * S_ + p] != 0) : 0;
        }
        __syncthreads();
        int jbase = t * 64;
        for (int jj = 0; jj < 64; jj++) {
            int j = jbase + jj;
            if (j < qi || j > qi + 2 * W_ || !vld[jj]) continue;
            float s = 0.f;
#pragma unroll
            for (int d = 0; d < HD_; d += 4) {
                float4 k4 = *reinterpret_cast<const float4*>(&ks[jj][d]);
                s = fmaf(qr[d], k4.x, s); s = fmaf(qr[d + 1], k4.y, s);
                s = fmaf(qr[d + 2], k4.z, s); s = fmaf(qr[d + 3], k4.w, s);
            }
            if (s > m) {
                float corr = expf(m - s);
                l *= corr;
#pragma unroll
                for (int d = 0; d < HD_; d++) acc[d] *= corr;
                m = s;
            }
            float w = expf(s - m);
            l += w;
#pragma unroll
            for (int d = 0; d < HD_; d += 4) {
                float4 v4 = *reinterpret_cast<const float4*>(&vs[jj][d]);
                acc[d]     = fmaf(w, v4.x, acc[d]);
                acc[d + 1] = fmaf(w, v4.y, acc[d + 1]);
                acc[d + 2] = fmaf(w, v4.z, acc[d + 2]);
                acc[d + 3] = fmaf(w, v4.w, acc[d + 3]);
            }
        }
    }
    float inv = 1.f / l;
    float* op = out + qoff;
#pragma unroll
    for (int d = 0; d < HD_; d++) op[d] = acc[d] * inv;
}

// ---------------- global-token attention -> overwrite out row 0 ----------------
__global__ void gattn_kernel(const float* __restrict__ qg, const float* __restrict__ kg,
                             const float* __restrict__ vg, const int* __restrict__ mask,
                             float* __restrict__ out) {
    const int hh = blockIdx.x, b = blockIdx.y;
    const int tid = threadIdx.x;   // 256
    __shared__ float sc[S_];
    __shared__ float qs[HD_];
    __shared__ float r1[8];
    __shared__ float stat[2];
    if (tid < HD_) qs[tid] = qg[b * D_ + hh * HD_ + tid];
    __syncthreads();
    float lmax = -3.4e38f;
    for (int s = tid; s < S_; s += 256) {
        const float* kr = kg + ((size_t)b * S_ + s) * D_ + hh * HD_;
        float dot = 0.f;
#pragma unroll
        for (int d = 0; d < HD_; d++) dot = fmaf(qs[d], kr[d], dot);
        if (mask[(size_t)b * S_ + s] == 0) dot = -1e9f;
        sc[s] = dot;
        lmax = fmaxf(lmax, dot);
    }
    {
        int lane = tid & 31, wid = tid >> 5;
#pragma unroll
        for (int o = 16; o > 0; o >>= 1) lmax = fmaxf(lmax, __shfl_down_sync(0xffffffffu, lmax, o));
        if (lane == 0) r1[wid] = lmax;
        __syncthreads();
        if (tid == 0) {
            float m2 = r1[0];
            for (int i = 1; i < 8; i++) m2 = fmaxf(m2, r1[i]);
            stat[0] = m2;
        }
        __syncthreads();
    }
    float gmax = stat[0];
    float lsum = 0.f;
    for (int s = tid; s < S_; s += 256) {
        float e = expf(sc[s] - gmax);
        sc[s] = e;
        lsum += e;
    }
    __syncthreads();
    {
        int lane = tid & 31, wid = tid >> 5;
#pragma unroll
        for (int o = 16; o > 0; o >>= 1) lsum += __shfl_down_sync(0xffffffffu, lsum, o);
        if (lane == 0) r1[wid] = lsum;
        __syncthreads();
        if (tid == 0) {
            float s2 = 0.f;
            for (int i = 0; i < 8; i++) s2 += r1[i];
            stat[1] = s2;
        }
        __syncthreads();
    }
    float inv = 1.f / stat[1];
    if (tid < HD_) {
        float a = 0.f;
        for (int s = 0; s < S_; s++)
            a = fmaf(sc[s], vg[((size_t)b * S_ + s) * D_ + hh * HD_ + tid], a);
        out[(size_t)b * S_ * D_ + hh * HD_ + tid] = a * inv;
    }
}

// ---------------- classifier head ----------------
__global__ void cls_kernel(const float* __restrict__ h, const float* __restrict__ Wcls,
                           const float* __restrict__ bcls, const int* __restrict__ mask,
                           float* __restrict__ out) {
    int w = threadIdx.x >> 5, lane = threadIdx.x & 31;   // 6 warps
    int b = w & 1, j = w >> 1;
    float s = 0.f;
    for (int kk = lane; kk < D_; kk += 32)
        s = fmaf(h[(size_t)b * S_ * D_ + kk], Wcls[kk * 3 + j], s);
#pragma unroll
    for (int o = 16; o > 0; o >>= 1) s += __shfl_down_sync(0xffffffffu, s, o);
    if (lane == 0) out[j * 2 + b] = 1.f / (1.f + expf(-(s + bcls[j])));
    if (threadIdx.x < 2) out[6 + threadIdx.x] = (float)mask[(size_t)threadIdx.x * S_];
}

// ---------------- launch ----------------
extern "C" void kernel_launch(void* const* d_in, const int* in_sizes, int n_in,
                              void* d_out, int out_size) {
    const int*   src  = (const int*)d_in[0];
    const int*   mask = (const int*)d_in[1];
    const float* etok = (const float*)d_in[3];
    const float* epos = (const float*)d_in[4];
    const float* elns = (const float*)d_in[5];
    const float* elnb = (const float*)d_in[6];
    const float* Wq   = (const float*)d_in[7];   const float* bq_p  = (const float*)d_in[8];
    const float* Wk   = (const float*)d_in[9];   const float* bk_p  = (const float*)d_in[10];
    const float* Wv   = (const float*)d_in[11];  const float* bv_p  = (const float*)d_in[12];
    const float* Wo   = (const float*)d_in[13];  const float* bo_p  = (const float*)d_in[14];
    const float* Wqg  = (const float*)d_in[15];  const float* bqg_p = (const float*)d_in[16];
    const float* Wkg  = (const float*)d_in[17];  const float* bkg_p = (const float*)d_in[18];
    const float* Wvg  = (const float*)d_in[19];  const float* bvg_p = (const float*)d_in[20];
    const float* ln1s = (const float*)d_in[21];  const float* ln1b  = (const float*)d_in[22];
    const float* W1   = (const float*)d_in[23];  const float* b1_p  = (const float*)d_in[24];
    const float* W2   = (const float*)d_in[25];  const float* b2_p  = (const float*)d_in[26];
    const float* ln2s = (const float*)d_in[27];  const float* ln2b  = (const float*)d_in[28];
    const float* Wcls = (const float*)d_in[29];  const float* bcls  = (const float*)d_in[30];
    float* out = (float*)d_out;

    float *ph, *pq, *pk, *pv, *pkg, *pvg, *pa, *pt, *pf, *pqg;
    cudaGetSymbolAddress((void**)&ph,  g_h);
    cudaGetSymbolAddress((void**)&pq,  g_q);
    cudaGetSymbolAddress((void**)&pk,  g_k);
    cudaGetSymbolAddress((void**)&pv,  g_v);
    cudaGetSymbolAddress((void**)&pkg, g_kg);
    cudaGetSymbolAddress((void**)&pvg, g_vg);
    cudaGetSymbolAddress((void**)&pa,  g_a);
    cudaGetSymbolAddress((void**)&pt,  g_t);
    cudaGetSymbolAddress((void**)&pf,  g_ff);
    cudaGetSymbolAddress((void**)&pqg, g_qg);

    const int M = B_ * S_;   // 4096

    embed_ln_kernel<<<M, 256>>>(src, etok, epos, elns, elnb, ph);

    for (int l = 0; l < L_; l++) {
        size_t wo  = (size_t)l * D_ * D_;
        size_t bof = (size_t)l * D_;
        dim3 gD(D_ / 64, M / 64);
        gemm_kernel<0><<<gD, 256>>>(ph, Wq  + wo, bq_p  + bof, pq,  M, D_, D_, 0.125f);
        gemm_kernel<0><<<gD, 256>>>(ph, Wk  + wo, bk_p  + bof, pk,  M, D_, D_, 1.f);
        gemm_kernel<0><<<gD, 256>>>(ph, Wv  + wo, bv_p  + bof, pv,  M, D_, D_, 1.f);
        gemm_kernel<0><<<gD, 256>>>(ph, Wkg + wo, bkg_p + bof, pkg, M, D_, D_, 1.f);
        gemm_kernel<0><<<gD, 256>>>(ph, Wvg + wo, bvg_p + bof, pvg, M, D_, D_, 1.f);
        qg_kernel<<<dim3(B_, 3), 256>>>(ph, Wqg + wo, bqg_p + bof, pqg);
        attn_kernel<<<dim3(NC_, H_, B_), 128>>>(pq, pk, pv, mask, pa);
        gattn_kernel<<<dim3(H_, B_), 256>>>(pqg, pkg, pvg, mask, pa);
        gemm_kernel<0><<<gD, 256>>>(pa, Wo + wo, bo_p + bof, pt, M, D_, D_, 1.f);
        add_ln_kernel<<<M, 256>>>(ph, pt, ln1s + bof, ln1b + bof);
        gemm_kernel<1><<<dim3(FF_ / 64, M / 64), 256>>>(ph, W1 + (size_t)l * D_ * FF_,
                                                        b1_p + (size_t)l * FF_, pf, M, FF_, D_, 1.f);
        gemm_kernel<0><<<gD, 256>>>(pf, W2 + (size_t)l * FF_ * D_, b2_p + bof, pt, M, D_, FF_, 1.f);
        add_ln_kernel<<<M, 256>>>(ph, pt, ln2s + bof, ln2b + bof);
    }

    cls_kernel<<<1, 192>>>(ph, Wcls, bcls, mask, out);
}

// round 2
// speedup vs baseline: 2.1936x; 2.1936x over previous
#include <cuda_runtime.h>
#include <math.h>

#define B_  2
#define S_  2048
#define D_  768
#define H_  12
#define HD_ 64
#define L_  4
#define FF_ 3072
#define NC_ 16
#define W_  128

// ---------------- scratch (static device arrays; no allocation) ----------------
__device__ float g_h [B_*S_*D_];
__device__ float g_q [B_*S_*D_];
__device__ float g_k [B_*S_*D_];
__device__ float g_v [B_*S_*D_];
__device__ float g_kg[B_*S_*D_];
__device__ float g_vg[B_*S_*D_];
__device__ float g_a [B_*S_*D_];
__device__ float g_t [B_*S_*D_];
__device__ float g_ff[B_*S_*FF_];
__device__ float g_qg[B_*D_];

// ---------------- helpers ----------------
__device__ __forceinline__ unsigned f2tf(float x) {
    unsigned r;
    asm("cvt.rna.tf32.f32 %0, %1;" : "=r"(r) : "f"(x));
    return r;
}

__device__ __forceinline__ void mma_tf32(float* c, const unsigned* a, const unsigned* b) {
    asm volatile(
        "mma.sync.aligned.m16n8k8.row.col.f32.tf32.tf32.f32 "
        "{%0,%1,%2,%3}, {%4,%5,%6,%7}, {%8,%9}, {%0,%1,%2,%3};"
        : "+f"(c[0]), "+f"(c[1]), "+f"(c[2]), "+f"(c[3])
        : "r"(a[0]), "r"(a[1]), "r"(a[2]), "r"(a[3]), "r"(b[0]), "r"(b[1]));
}

__device__ __forceinline__ void block_reduce2(float a, float b, float* out2) {
    __shared__ float r1[8], r2[8];
    int lane = threadIdx.x & 31, wid = threadIdx.x >> 5;
#pragma unroll
    for (int o = 16; o > 0; o >>= 1) {
        a += __shfl_down_sync(0xffffffffu, a, o);
        b += __shfl_down_sync(0xffffffffu, b, o);
    }
    if (lane == 0) { r1[wid] = a; r2[wid] = b; }
    __syncthreads();
    if (wid == 0) {
        int nw = blockDim.x >> 5;
        a = (lane < nw) ? r1[lane] : 0.f;
        b = (lane < nw) ? r2[lane] : 0.f;
#pragma unroll
        for (int o = 4; o > 0; o >>= 1) {
            a += __shfl_down_sync(0xffffffffu, a, o);
            b += __shfl_down_sync(0xffffffffu, b, o);
        }
        if (lane == 0) { out2[0] = a; out2[1] = b; }
    }
    __syncthreads();
}

// ---------------- tf32 tensor-core GEMM core ----------------
// C = act((A@B + bias) * alpha); A: MxK rm, B: KxN rm. M%128==N%128==K%16==0.
// Block 128x128x16, 256 thr, 8 warps in 2x4 (warp tile 64x32), double-buffered.
template <int ACT>
__device__ __forceinline__ void gemm_core(
    const float* __restrict__ A, const float* __restrict__ Bm,
    const float* __restrict__ bias, float* __restrict__ C,
    int M, int N, int K, float alpha) {
    __shared__ unsigned As[2][128 * 20];   // row stride 20 (pad 16->20)
    __shared__ unsigned Bs[2][16 * 136];   // row stride 136 (pad 128->136)

    const int tid = threadIdx.x, lane = tid & 31, wid = tid >> 5;
    const int wm = (wid >> 2) * 64, wn = (wid & 3) * 32;
    const int g = lane >> 2, t = lane & 3;
    const int bm = blockIdx.y * 128, bn = blockIdx.x * 128;

    int arow[2], ac4[2], brow[2], bc4[2];
#pragma unroll
    for (int i = 0; i < 2; i++) {
        int f = tid + i * 256;
        arow[i] = f >> 2;  ac4[i] = f & 3;     // A tile: 128 rows x 4 float4
        brow[i] = f >> 5;  bc4[i] = f & 31;    // B tile: 16 rows x 32 float4
    }

    float4 ar[2], br[2];
    float acc[4][4][4];
#pragma unroll
    for (int i = 0; i < 4; i++)
#pragma unroll
        for (int j = 0; j < 4; j++)
#pragma unroll
            for (int r = 0; r < 4; r++) acc[i][j][r] = 0.f;

    // prologue: tile 0
#pragma unroll
    for (int i = 0; i < 2; i++) {
        ar[i] = *(const float4*)(A + (size_t)(bm + arow[i]) * K + ac4[i] * 4);
        br[i] = *(const float4*)(Bm + (size_t)brow[i] * N + bn + bc4[i] * 4);
    }
#pragma unroll
    for (int i = 0; i < 2; i++) {
        unsigned* pa = &As[0][arow[i] * 20 + ac4[i] * 4];
        pa[0] = f2tf(ar[i].x); pa[1] = f2tf(ar[i].y); pa[2] = f2tf(ar[i].z); pa[3] = f2tf(ar[i].w);
        unsigned* pb = &Bs[0][brow[i] * 136 + bc4[i] * 4];
        pb[0] = f2tf(br[i].x); pb[1] = f2tf(br[i].y); pb[2] = f2tf(br[i].z); pb[3] = f2tf(br[i].w);
    }
    __syncthreads();

    const int nk = K >> 4;
    for (int kt = 0; kt < nk; kt++) {
        const int buf = kt & 1;
        const bool hasNext = (kt + 1 < nk);
        if (hasNext) {
            int k0 = (kt + 1) << 4;
#pragma unroll
            for (int i = 0; i < 2; i++) {
                ar[i] = *(const float4*)(A + (size_t)(bm + arow[i]) * K + k0 + ac4[i] * 4);
                br[i] = *(const float4*)(Bm + (size_t)(k0 + brow[i]) * N + bn + bc4[i] * 4);
            }
        }
#pragma unroll
        for (int ks = 0; ks < 2; ks++) {
            const int kb = ks * 8;
            unsigned af[4][4], bf[4][2];
#pragma unroll
            for (int mt = 0; mt < 4; mt++) {
                int r = wm + mt * 16 + g;
                af[mt][0] = As[buf][r * 20 + kb + t];
                af[mt][1] = As[buf][(r + 8) * 20 + kb + t];
                af[mt][2] = As[buf][r * 20 + kb + t + 4];
                af[mt][3] = As[buf][(r + 8) * 20 + kb + t + 4];
            }
#pragma unroll
            for (int nt = 0; nt < 4; nt++) {
                int cc = wn + nt * 8 + g;
                bf[nt][0] = Bs[buf][(kb + t) * 136 + cc];
                bf[nt][1] = Bs[buf][(kb + t + 4) * 136 + cc];
            }
#pragma unroll
            for (int mt = 0; mt < 4; mt++)
#pragma unroll
                for (int nt = 0; nt < 4; nt++)
                    mma_tf32(acc[mt][nt], af[mt], bf[nt]);
        }
        if (hasNext) {
            int nb = buf ^ 1;
#pragma unroll
            for (int i = 0; i < 2; i++) {
                unsigned* pa = &As[nb][arow[i] * 20 + ac4[i] * 4];
                pa[0] = f2tf(ar[i].x); pa[1] = f2tf(ar[i].y); pa[2] = f2tf(ar[i].z); pa[3] = f2tf(ar[i].w);
                unsigned* pb = &Bs[nb][brow[i] * 136 + bc4[i] * 4];
                pb[0] = f2tf(br[i].x); pb[1] = f2tf(br[i].y); pb[2] = f2tf(br[i].z); pb[3] = f2tf(br[i].w);
            }
        }
        __syncthreads();
    }

    // epilogue
#pragma unroll
    for (int mt = 0; mt < 4; mt++) {
#pragma unroll
        for (int nt = 0; nt < 4; nt++) {
            int r0 = bm + wm + mt * 16 + g;
            int c0 = bn + wn + nt * 8 + t * 2;
            float b0 = bias[c0], b1 = bias[c0 + 1];
            float v[4];
            v[0] = (acc[mt][nt][0] + b0) * alpha;
            v[1] = (acc[mt][nt][1] + b1) * alpha;
            v[2] = (acc[mt][nt][2] + b0) * alpha;
            v[3] = (acc[mt][nt][3] + b1) * alpha;
            if (ACT == 1) {
#pragma unroll
                for (int i = 0; i < 4; i++)
                    v[i] = 0.5f * v[i] * (1.f + erff(v[i] * 0.7071067811865476f));
            }
            *(float2*)(C + (size_t)r0 * N + c0)       = make_float2(v[0], v[1]);
            *(float2*)(C + (size_t)(r0 + 8) * N + c0) = make_float2(v[2], v[3]);
        }
    }
}

template <int ACT>
__global__ void __launch_bounds__(256) tgemm_kernel(
    const float* __restrict__ A, const float* __restrict__ Bm,
    const float* __restrict__ bias, float* __restrict__ C,
    int M, int N, int K, float alpha) {
    gemm_core<ACT>(A, Bm, bias, C, M, N, K, alpha);
}

// batched projections (shared A = h): z picks weight/bias/out/alpha
struct ProjParams {
    const float* W[5];
    const float* b[5];
    float*       o[5];
    float        alpha[5];
};

__global__ void __launch_bounds__(256) proj_gemm_kernel(
    const float* __restrict__ A, ProjParams p, int M, int N, int K) {
    int z = blockIdx.z;
    gemm_core<0>(A, p.W[z], p.b[z], p.o[z], M, N, K, p.alpha[z]);
}

// ---------------- embedding + LN ----------------
__global__ void embed_ln_kernel(const int* __restrict__ src,
                                const float* __restrict__ etok,
                                const float* __restrict__ epos,
                                const float* __restrict__ gs,
                                const float* __restrict__ gb,
                                float* __restrict__ h) {
    int tok = blockIdx.x;
    int s   = tok & (S_ - 1);
    int tid = threadIdx.x;
    __shared__ float stat[2];
    size_t row = (size_t)src[tok] * D_;
    float vals[3]; float sum = 0.f, sq = 0.f;
#pragma unroll
    for (int i = 0; i < 3; i++) {
        int d = tid + i * 256;
        float v = etok[row + d] + epos[(size_t)s * D_ + d];
        vals[i] = v; sum += v; sq += v * v;
    }
    block_reduce2(sum, sq, stat);
    float mean = stat[0] * (1.f / D_);
    float var  = stat[1] * (1.f / D_) - mean * mean;
    float inv  = 1.f / sqrtf(var + 1e-5f);
#pragma unroll
    for (int i = 0; i < 3; i++) {
        int d = tid + i * 256;
        h[(size_t)tok * D_ + d] = (vals[i] - mean) * inv * gs[d] + gb[d];
    }
}

// ---------------- residual add + LN (in place on h) ----------------
__global__ void add_ln_kernel(float* __restrict__ h, const float* __restrict__ x,
                              const float* __restrict__ sc, const float* __restrict__ bi) {
    int tok = blockIdx.x;
    int tid = threadIdx.x;
    __shared__ float stat[2];
    float* hp = h + (size_t)tok * D_;
    const float* xp = x + (size_t)tok * D_;
    float vals[3]; float sum = 0.f, sq = 0.f;
#pragma unroll
    for (int i = 0; i < 3; i++) {
        int d = tid + i * 256;
        float v = hp[d] + xp[d];
        vals[i] = v; sum += v; sq += v * v;
    }
    block_reduce2(sum, sq, stat);
    float mean = stat[0] * (1.f / D_);
    float var  = stat[1] * (1.f / D_) - mean * mean;
    float inv  = 1.f / sqrtf(var + 1e-5f);
#pragma unroll
    for (int i = 0; i < 3; i++) {
        int d = tid + i * 256;
        hp[d] = (vals[i] - mean) * inv * sc[d] + bi[d];
    }
}

// ---------------- qg = (h[:,0,:] @ Wqg + bqg) / 8 ----------------
__global__ void qg_kernel(const float* __restrict__ h, const float* __restrict__ Wm,
                          const float* __restrict__ bias, float* __restrict__ qg) {
    int b = blockIdx.x;
    int j = blockIdx.y * 256 + threadIdx.x;
    __shared__ float hs[D_];
    for (int i = threadIdx.x; i < D_; i += 256) hs[i] = h[(size_t)b * S_ * D_ + i];
    __syncthreads();
    float s = 0.f;
    for (int kk = 0; kk < D_; kk++) s = fmaf(hs[kk], Wm[(size_t)kk * D_ + j], s);
    qg[b * D_ + j] = (s + bias[j]) * 0.125f;
}

// ---------------- sliding-window + global-key attention (flash-style) ----------------
__global__ void __launch_bounds__(128) attn_kernel(
    const float* __restrict__ q, const float* __restrict__ k, const float* __restrict__ v,
    const int* __restrict__ mask, float* __restrict__ out) {
    const int c = blockIdx.x, hh = blockIdx.y, b = blockIdx.z;
    const int qi = threadIdx.x;
    __shared__ float ks[64][HD_];
    __shared__ float vs[64][HD_];
    __shared__ int vld[64];
    const size_t qoff = ((size_t)b * S_ + c * W_ + qi) * D_ + hh * HD_;
    float qr[HD_], acc[HD_];
#pragma unroll
    for (int d = 0; d < HD_; d += 4) {
        float4 tq = *reinterpret_cast<const float4*>(q + qoff + d);
        qr[d] = tq.x; qr[d + 1] = tq.y; qr[d + 2] = tq.z; qr[d + 3] = tq.w;
    }
    float m = -1e30f, l = 0.f;
#pragma unroll
    for (int d = 0; d < HD_; d++) acc[d] = 0.f;

    if (mask[(size_t)b * S_] != 0) {
        const size_t koff = ((size_t)b * S_) * D_ + hh * HD_;
        float s = 0.f;
#pragma unroll
        for (int d = 0; d < HD_; d++) s = fmaf(qr[d], k[koff + d], s);
        m = s; l = 1.f;
#pragma unroll
        for (int d = 0; d < HD_; d++) acc[d] = v[koff + d];
    }

    for (int t = 0; t < 6; t++) {
        __syncthreads();
        for (int e = qi; e < 64 * HD_; e += 128) {
            int r = e >> 6, d = e & 63;
            int p = c * W_ - W_ + t * 64 + r;
            float kv = 0.f, vv = 0.f;
            if (p >= 0 && p < S_) {
                size_t off = ((size_t)b * S_ + p) * D_ + hh * HD_ + d;
                kv = k[off]; vv = v[off];
            }
            ks[r][d] = kv; vs[r][d] = vv;
        }
        if (qi < 64) {
            int p = c * W_ - W_ + t * 64 + qi;
            vld[qi] = (p >= 0 && p < S_) ? (mask[(size_t)b * S_ + p] != 0) : 0;
        }
        __syncthreads();
        int jbase = t * 64;
        for (int jj = 0; jj < 64; jj++) {
            int j = jbase + jj;
            if (j < qi || j > qi + 2 * W_ || !vld[jj]) continue;
            float s = 0.f;
#pragma unroll
            for (int d = 0; d < HD_; d += 4) {
                float4 k4 = *reinterpret_cast<const float4*>(&ks[jj][d]);
                s = fmaf(qr[d], k4.x, s); s = fmaf(qr[d + 1], k4.y, s);
                s = fmaf(qr[d + 2], k4.z, s); s = fmaf(qr[d + 3], k4.w, s);
            }
            if (s > m) {
                float corr = expf(m - s);
                l *= corr;
#pragma unroll
                for (int d = 0; d < HD_; d++) acc[d] *= corr;
                m = s;
            }
            float w = expf(s - m);
            l += w;
#pragma unroll
            for (int d = 0; d < HD_; d += 4) {
                float4 v4 = *reinterpret_cast<const float4*>(&vs[jj][d]);
                acc[d]     = fmaf(w, v4.x, acc[d]);
                acc[d + 1] = fmaf(w, v4.y, acc[d + 1]);
                acc[d + 2] = fmaf(w, v4.z, acc[d + 2]);
                acc[d + 3] = fmaf(w, v4.w, acc[d + 3]);
            }
        }
    }
    float inv = 1.f / l;
    float* op = out + qoff;
#pragma unroll
    for (int d = 0; d < HD_; d++) op[d] = acc[d] * inv;
}

// ---------------- global-token attention -> overwrite out row 0 ----------------
__global__ void gattn_kernel(const float* __restrict__ qg, const float* __restrict__ kg,
                             const float* __restrict__ vg, const int* __restrict__ mask,
                             float* __restrict__ out) {
    const int hh = blockIdx.x, b = blockIdx.y;
    const int tid = threadIdx.x;
    __shared__ float sc[S_];
    __shared__ float qs[HD_];
    __shared__ float r1[8];
    __shared__ float stat[2];
    if (tid < HD_) qs[tid] = qg[b * D_ + hh * HD_ + tid];
    __syncthreads();
    float lmax = -3.4e38f;
    for (int s = tid; s < S_; s += 256) {
        const float* kr = kg + ((size_t)b * S_ + s) * D_ + hh * HD_;
        float dot = 0.f;
#pragma unroll
        for (int d = 0; d < HD_; d++) dot = fmaf(qs[d], kr[d], dot);
        if (mask[(size_t)b * S_ + s] == 0) dot = -1e9f;
        sc[s] = dot;
        lmax = fmaxf(lmax, dot);
    }
    {
        int lane = tid & 31, wid = tid >> 5;
#pragma unroll
        for (int o = 16; o > 0; o >>= 1) lmax = fmaxf(lmax, __shfl_down_sync(0xffffffffu, lmax, o));
        if (lane == 0) r1[wid] = lmax;
        __syncthreads();
        if (tid == 0) {
            float m2 = r1[0];
            for (int i = 1; i < 8; i++) m2 = fmaxf(m2, r1[i]);
            stat[0] = m2;
        }
        __syncthreads();
    }
    float gmax = stat[0];
    float lsum = 0.f;
    for (int s = tid; s < S_; s += 256) {
        float e = expf(sc[s] - gmax);
        sc[s] = e;
        lsum += e;
    }
    __syncthreads();
    {
        int lane = tid & 31, wid = tid >> 5;
#pragma unroll
        for (int o = 16; o > 0; o >>= 1) lsum += __shfl_down_sync(0xffffffffu, lsum, o);
        if (lane == 0) r1[wid] = lsum;
        __syncthreads();
        if (tid == 0) {
            float s2 = 0.f;
            for (int i = 0; i < 8; i++) s2 += r1[i];
            stat[1] = s2;
        }
        __syncthreads();
    }
    float inv = 1.f / stat[1];
    if (tid < HD_) {
        float a = 0.f;
        for (int s = 0; s < S_; s++)
            a = fmaf(sc[s], vg[((size_t)b * S_ + s) * D_ + hh * HD_ + tid], a);
        out[(size_t)b * S_ * D_ + hh * HD_ + tid] = a * inv;
    }
}

// ---------------- classifier head ----------------
__global__ void cls_kernel(const float* __restrict__ h, const float* __restrict__ Wcls,
                           const float* __restrict__ bcls, const int* __restrict__ mask,
                           float* __restrict__ out) {
    int w = threadIdx.x >> 5, lane = threadIdx.x & 31;
    int b = w & 1, j = w >> 1;
    float s = 0.f;
    for (int kk = lane; kk < D_; kk += 32)
        s = fmaf(h[(size_t)b * S_ * D_ + kk], Wcls[kk * 3 + j], s);
#pragma unroll
    for (int o = 16; o > 0; o >>= 1) s += __shfl_down_sync(0xffffffffu, s, o);
    if (lane == 0) out[j * 2 + b] = 1.f / (1.f + expf(-(s + bcls[j])));
    if (threadIdx.x < 2) out[6 + threadIdx.x] = (float)mask[(size_t)threadIdx.x * S_];
}

// ---------------- launch ----------------
extern "C" void kernel_launch(void* const* d_in, const int* in_sizes, int n_in,
                              void* d_out, int out_size) {
    const int*   src  = (const int*)d_in[0];
    const int*   mask = (const int*)d_in[1];
    const float* etok = (const float*)d_in[3];
    const float* epos = (const float*)d_in[4];
    const float* elns = (const float*)d_in[5];
    const float* elnb = (const float*)d_in[6];
    const float* Wq   = (const float*)d_in[7];   const float* bq_p  = (const float*)d_in[8];
    const float* Wk   = (const float*)d_in[9];   const float* bk_p  = (const float*)d_in[10];
    const float* Wv   = (const float*)d_in[11];  const float* bv_p  = (const float*)d_in[12];
    const float* Wo   = (const float*)d_in[13];  const float* bo_p  = (const float*)d_in[14];
    const float* Wqg  = (const float*)d_in[15];  const float* bqg_p = (const float*)d_in[16];
    const float* Wkg  = (const float*)d_in[17];  const float* bkg_p = (const float*)d_in[18];
    const float* Wvg  = (const float*)d_in[19];  const float* bvg_p = (const float*)d_in[20];
    const float* ln1s = (const float*)d_in[21];  const float* ln1b  = (const float*)d_in[22];
    const float* W1   = (const float*)d_in[23];  const float* b1_p  = (const float*)d_in[24];
    const float* W2   = (const float*)d_in[25];  const float* b2_p  = (const float*)d_in[26];
    const float* ln2s = (const float*)d_in[27];  const float* ln2b  = (const float*)d_in[28];
    const float* Wcls = (const float*)d_in[29];  const float* bcls  = (const float*)d_in[30];
    float* out = (float*)d_out;

    float *ph, *pq, *pk, *pv, *pkg, *pvg, *pa, *pt, *pf, *pqg;
    cudaGetSymbolAddress((void**)&ph,  g_h);
    cudaGetSymbolAddress((void**)&pq,  g_q);
    cudaGetSymbolAddress((void**)&pk,  g_k);
    cudaGetSymbolAddress((void**)&pv,  g_v);
    cudaGetSymbolAddress((void**)&pkg, g_kg);
    cudaGetSymbolAddress((void**)&pvg, g_vg);
    cudaGetSymbolAddress((void**)&pa,  g_a);
    cudaGetSymbolAddress((void**)&pt,  g_t);
    cudaGetSymbolAddress((void**)&pf,  g_ff);
    cudaGetSymbolAddress((void**)&pqg, g_qg);

    const int M = B_ * S_;   // 4096

    embed_ln_kernel<<<M, 256>>>(src, etok, epos, elns, elnb, ph);

    for (int l = 0; l < L_; l++) {
        size_t wo  = (size_t)l * D_ * D_;
        size_t bof = (size_t)l * D_;

        ProjParams pp;
        pp.W[0] = Wq  + wo; pp.b[0] = bq_p  + bof; pp.o[0] = pq;  pp.alpha[0] = 0.125f;
        pp.W[1] = Wk  + wo; pp.b[1] = bk_p  + bof; pp.o[1] = pk;  pp.alpha[1] = 1.f;
        pp.W[2] = Wv  + wo; pp.b[2] = bv_p  + bof; pp.o[2] = pv;  pp.alpha[2] = 1.f;
        pp.W[3] = Wkg + wo; pp.b[3] = bkg_p + bof; pp.o[3] = pkg; pp.alpha[3] = 1.f;
        pp.W[4] = Wvg + wo; pp.b[4] = bvg_p + bof; pp.o[4] = pvg; pp.alpha[4] = 1.f;
        proj_gemm_kernel<<<dim3(D_ / 128, M / 128, 5), 256>>>(ph, pp, M, D_, D_);

        qg_kernel<<<dim3(B_, 3), 256>>>(ph, Wqg + wo, bqg_p + bof, pqg);
        attn_kernel<<<dim3(NC_, H_, B_), 128>>>(pq, pk, pv, mask, pa);
        gattn_kernel<<<dim3(H_, B_), 256>>>(pqg, pkg, pvg, mask, pa);

        tgemm_kernel<0><<<dim3(D_ / 128, M / 128), 256>>>(pa, Wo + wo, bo_p + bof, pt, M, D_, D_, 1.f);
        add_ln_kernel<<<M, 256>>>(ph, pt, ln1s + bof, ln1b + bof);
        tgemm_kernel<1><<<dim3(FF_ / 128, M / 128), 256>>>(ph, W1 + (size_t)l * D_ * FF_,
                                                           b1_p + (size_t)l * FF_, pf, M, FF_, D_, 1.f);
        tgemm_kernel<0><<<dim3(D_ / 128, M / 128), 256>>>(pf, W2 + (size_t)l * FF_ * D_,
                                                          b2_p + bof, pt, M, D_, FF_, 1.f);
        add_ln_kernel<<<M, 256>>>(ph, pt, ln2s + bof, ln2b + bof);
    }

    cls_kernel<<<1, 192>>>(ph, Wcls, bcls, mask, out);
}

// round 3
// speedup vs baseline: 2.4780x; 1.1297x over previous
#include <cuda_runtime.h>
#include <math.h>
#include <stdint.h>

#define B_  2
#define S_  2048
#define D_  768
#define H_  12
#define HD_ 64
#define L_  4
#define FF_ 3072
#define NC_ 16
#define W_  128

// ---------------- scratch (static device arrays; no allocation) ----------------
__device__ float g_h [B_*S_*D_];
__device__ float g_q [B_*S_*D_];
__device__ float g_k [B_*S_*D_];
__device__ float g_v [B_*S_*D_];
__device__ float g_kg[B_*S_*D_];
__device__ float g_vg[B_*S_*D_];
__device__ float g_a [B_*S_*D_];
__device__ float g_t [B_*S_*D_];
__device__ float g_ff[B_*S_*FF_];
__device__ float g_qg[B_*D_];

// ---------------- helpers ----------------
__device__ __forceinline__ uint32_t smem_u32(const void* p) {
    return (uint32_t)__cvta_generic_to_shared(p);
}
__device__ __forceinline__ void cp16(uint32_t dst, const void* src) {
    asm volatile("cp.async.cg.shared.global [%0], [%1], 16;" :: "r"(dst), "l"(src));
}
__device__ __forceinline__ void cp_commit() { asm volatile("cp.async.commit_group;"); }
template <int N> __device__ __forceinline__ void cp_wait() {
    asm volatile("cp.async.wait_group %0;" :: "n"(N));
}

__device__ __forceinline__ void mma_tf32(float* c, const unsigned* a, const unsigned* b) {
    asm volatile(
        "mma.sync.aligned.m16n8k8.row.col.f32.tf32.tf32.f32 "
        "{%0,%1,%2,%3}, {%4,%5,%6,%7}, {%8,%9}, {%0,%1,%2,%3};"
        : "+f"(c[0]), "+f"(c[1]), "+f"(c[2]), "+f"(c[3])
        : "r"(a[0]), "r"(a[1]), "r"(a[2]), "r"(a[3]), "r"(b[0]), "r"(b[1]));
}

__device__ __forceinline__ void block_reduce2(float a, float b, float* out2) {
    __shared__ float r1[8], r2[8];
    int lane = threadIdx.x & 31, wid = threadIdx.x >> 5;
#pragma unroll
    for (int o = 16; o > 0; o >>= 1) {
        a += __shfl_down_sync(0xffffffffu, a, o);
        b += __shfl_down_sync(0xffffffffu, b, o);
    }
    if (lane == 0) { r1[wid] = a; r2[wid] = b; }
    __syncthreads();
    if (wid == 0) {
        int nw = blockDim.x >> 5;
        a = (lane < nw) ? r1[lane] : 0.f;
        b = (lane < nw) ? r2[lane] : 0.f;
#pragma unroll
        for (int o = 4; o > 0; o >>= 1) {
            a += __shfl_down_sync(0xffffffffu, a, o);
            b += __shfl_down_sync(0xffffffffu, b, o);
        }
        if (lane == 0) { out2[0] = a; out2[1] = b; }
    }
    __syncthreads();
}

// ---------------- tf32 tensor-core GEMM, cp.async double-buffered ----------------
// C = act((A@B + bias) * alpha); A: MxK rm, B: KxN rm. M%128==N%128==K%16==0.
// Block 128x128x16, 256 thr, 8 warps 2x4 (warp tile 64x32). Raw fp32 bits into
// mma.tf32 (hw truncates mantissa). A smem: stride 16, XOR swizzle on k bits 2:3.
// B smem: stride 136 (16B-aligned, conflict-free fragment reads).
template <int ACT>
__device__ __forceinline__ void gemm_core(
    const float* __restrict__ A, const float* __restrict__ Bm,
    const float* __restrict__ bias, float* __restrict__ C,
    int M, int N, int K, float alpha) {
    __shared__ uint32_t As[2][128 * 16];
    __shared__ uint32_t Bs[2][16 * 136];

    const int tid = threadIdx.x, lane = tid & 31, wid = tid >> 5;
    const int wm = (wid >> 2) * 64, wn = (wid & 3) * 32;
    const int g = lane >> 2, t = lane & 3;
    const int bm = blockIdx.y * 128, bn = blockIdx.x * 128;

    // cp.async addressing: A chunks (row=tid>>2 [+64], logical kchunk=tid&3),
    // phys kchunk = logical ^ (row&3). B chunks (krow=tid>>5 [+8], nchunk=tid&31).
    const int arow = tid >> 2, ac4 = tid & 3;
    const int axc  = ac4 ^ (arow & 3);
    const int brow = tid >> 5, bc4 = tid & 31;

    uint32_t aDst[2], bDst[2];
    aDst[0] = smem_u32(&As[0][arow * 16 + axc * 4]);
    aDst[1] = smem_u32(&As[1][arow * 16 + axc * 4]);
    bDst[0] = smem_u32(&Bs[0][brow * 136 + bc4 * 4]);
    bDst[1] = smem_u32(&Bs[1][brow * 136 + bc4 * 4]);

    float acc[4][4][4];
#pragma unroll
    for (int i = 0; i < 4; i++)
#pragma unroll
        for (int j = 0; j < 4; j++)
#pragma unroll
            for (int r = 0; r < 4; r++) acc[i][j][r] = 0.f;

    const int nk = K >> 4;

    // issue stage 0
    {
        const float* a0 = A + (size_t)(bm + arow) * K + ac4 * 4;
        cp16(aDst[0], a0);
        cp16(aDst[0] + 64 * 16 * 4, a0 + (size_t)64 * K);
        const float* b0 = Bm + (size_t)brow * N + bn + bc4 * 4;
        cp16(bDst[0], b0);
        cp16(bDst[0] + 8 * 136 * 4, b0 + (size_t)8 * N);
        cp_commit();
    }

    for (int kt = 0; kt < nk; kt++) {
        cp_wait<0>();
        __syncthreads();
        if (kt + 1 < nk) {
            int slot = (kt + 1) & 1;
            int k0 = (kt + 1) << 4;
            const float* a0 = A + (size_t)(bm + arow) * K + k0 + ac4 * 4;
            cp16(aDst[slot], a0);
            cp16(aDst[slot] + 64 * 16 * 4, a0 + (size_t)64 * K);
            const float* b0 = Bm + (size_t)(k0 + brow) * N + bn + bc4 * 4;
            cp16(bDst[slot], b0);
            cp16(bDst[slot] + 8 * 136 * 4, b0 + (size_t)8 * N);
            cp_commit();
        }
        const uint32_t* sA = As[kt & 1];
        const uint32_t* sB = Bs[kt & 1];
        const int xo = (g & 3) << 2;
#pragma unroll
        for (int kb = 0; kb < 16; kb += 8) {
            const int k0x = (kb + t) ^ xo;
            const int k1x = (kb + t + 4) ^ xo;
            unsigned af[4][4], bf[4][2];
#pragma unroll
            for (int mt = 0; mt < 4; mt++) {
                int r = wm + mt * 16 + g;
                af[mt][0] = sA[r * 16 + k0x];
                af[mt][1] = sA[(r + 8) * 16 + k0x];
                af[mt][2] = sA[r * 16 + k1x];
                af[mt][3] = sA[(r + 8) * 16 + k1x];
            }
#pragma unroll
            for (int nt = 0; nt < 4; nt++) {
                int cc = wn + nt * 8 + g;
                bf[nt][0] = sB[(kb + t) * 136 + cc];
                bf[nt][1] = sB[(kb + t + 4) * 136 + cc];
            }
#pragma unroll
            for (int mt = 0; mt < 4; mt++)
#pragma unroll
                for (int nt = 0; nt < 4; nt++)
                    mma_tf32(acc[mt][nt], af[mt], bf[nt]);
        }
    }

    // epilogue
#pragma unroll
    for (int mt = 0; mt < 4; mt++) {
#pragma unroll
        for (int nt = 0; nt < 4; nt++) {
            int r0 = bm + wm + mt * 16 + g;
            int c0 = bn + wn + nt * 8 + t * 2;
            float b0 = bias[c0], b1 = bias[c0 + 1];
            float v[4];
            v[0] = (acc[mt][nt][0] + b0) * alpha;
            v[1] = (acc[mt][nt][1] + b1) * alpha;
            v[2] = (acc[mt][nt][2] + b0) * alpha;
            v[3] = (acc[mt][nt][3] + b1) * alpha;
            if (ACT == 1) {
#pragma unroll
                for (int i = 0; i < 4; i++)
                    v[i] = 0.5f * v[i] * (1.f + erff(v[i] * 0.7071067811865476f));
            }
            *(float2*)(C + (size_t)r0 * N + c0)       = make_float2(v[0], v[1]);
            *(float2*)(C + (size_t)(r0 + 8) * N + c0) = make_float2(v[2], v[3]);
        }
    }
}

template <int ACT>
__global__ void __launch_bounds__(256) tgemm_kernel(
    const float* __restrict__ A, const float* __restrict__ Bm,
    const float* __restrict__ bias, float* __restrict__ C,
    int M, int N, int K, float alpha) {
    gemm_core<ACT>(A, Bm, bias, C, M, N, K, alpha);
}

struct ProjParams {
    const float* W[5];
    const float* b[5];
    float*       o[5];
    float        alpha[5];
};

__global__ void __launch_bounds__(256) proj_gemm_kernel(
    const float* __restrict__ A, ProjParams p, int M, int N, int K) {
    int z = blockIdx.z;
    gemm_core<0>(A, p.W[z], p.b[z], p.o[z], M, N, K, p.alpha[z]);
}

// ---------------- embedding + LN ----------------
__global__ void embed_ln_kernel(const int* __restrict__ src,
                                const float* __restrict__ etok,
                                const float* __restrict__ epos,
                                const float* __restrict__ gs,
                                const float* __restrict__ gb,
                                float* __restrict__ h) {
    int tok = blockIdx.x;
    int s   = tok & (S_ - 1);
    int tid = threadIdx.x;
    __shared__ float stat[2];
    size_t row = (size_t)src[tok] * D_;
    float vals[3]; float sum = 0.f, sq = 0.f;
#pragma unroll
    for (int i = 0; i < 3; i++) {
        int d = tid + i * 256;
        float v = etok[row + d] + epos[(size_t)s * D_ + d];
        vals[i] = v; sum += v; sq += v * v;
    }
    block_reduce2(sum, sq, stat);
    float mean = stat[0] * (1.f / D_);
    float var  = stat[1] * (1.f / D_) - mean * mean;
    float inv  = 1.f / sqrtf(var + 1e-5f);
#pragma unroll
    for (int i = 0; i < 3; i++) {
        int d = tid + i * 256;
        h[(size_t)tok * D_ + d] = (vals[i] - mean) * inv * gs[d] + gb[d];
    }
}

// ---------------- residual add + LN (in place on h) ----------------
__global__ void add_ln_kernel(float* __restrict__ h, const float* __restrict__ x,
                              const float* __restrict__ sc, const float* __restrict__ bi) {
    int tok = blockIdx.x;
    int tid = threadIdx.x;
    __shared__ float stat[2];
    float* hp = h + (size_t)tok * D_;
    const float* xp = x + (size_t)tok * D_;
    float vals[3]; float sum = 0.f, sq = 0.f;
#pragma unroll
    for (int i = 0; i < 3; i++) {
        int d = tid + i * 256;
        float v = hp[d] + xp[d];
        vals[i] = v; sum += v; sq += v * v;
    }
    block_reduce2(sum, sq, stat);
    float mean = stat[0] * (1.f / D_);
    float var  = stat[1] * (1.f / D_) - mean * mean;
    float inv  = 1.f / sqrtf(var + 1e-5f);
#pragma unroll
    for (int i = 0; i < 3; i++) {
        int d = tid + i * 256;
        hp[d] = (vals[i] - mean) * inv * sc[d] + bi[d];
    }
}

// ---------------- qg = (h[:,0,:] @ Wqg + bqg) / 8 ----------------
__global__ void qg_kernel(const float* __restrict__ h, const float* __restrict__ Wm,
                          const float* __restrict__ bias, float* __restrict__ qg) {
    int b = blockIdx.x;
    int j = blockIdx.y * 256 + threadIdx.x;
    __shared__ float hs[D_];
    for (int i = threadIdx.x; i < D_; i += 256) hs[i] = h[(size_t)b * S_ * D_ + i];
    __syncthreads();
    float s = 0.f;
    for (int kk = 0; kk < D_; kk++) s = fmaf(hs[kk], Wm[(size_t)kk * D_ + j], s);
    qg[b * D_ + j] = (s + bias[j]) * 0.125f;
}

// ---------------- sliding-window + global-key attention ----------------
// 256 threads: qi = tid>>1 (query in chunk), half = tid&1 (d halves). Score halves
// combined via shfl_xor(1). Chunk-of-8 branchless online softmax. smem rows have
// half-1 data at +36 words so the two broadcast addresses hit disjoint banks.
__global__ void __launch_bounds__(256) attn_kernel(
    const float* __restrict__ q, const float* __restrict__ k, const float* __restrict__ v,
    const int* __restrict__ mask, float* __restrict__ out) {
    const int c = blockIdx.x, hh = blockIdx.y, b = blockIdx.z;
    const int tid = threadIdx.x;
    const int qi = tid >> 1, half = tid & 1;
    __shared__ float ks[64][72];
    __shared__ float vs[64][72];
    __shared__ int vld[64];
    const int hoff = half * 36;
    const size_t qoff = ((size_t)b * S_ + c * W_ + qi) * D_ + hh * HD_ + half * 32;
    float qr[32], acc[32];
#pragma unroll
    for (int i = 0; i < 8; i++) {
        float4 t4 = *(const float4*)(q + qoff + i * 4);
        qr[i*4] = t4.x; qr[i*4+1] = t4.y; qr[i*4+2] = t4.z; qr[i*4+3] = t4.w;
    }
    float m = -1e30f, l = 0.f;
#pragma unroll
    for (int i = 0; i < 32; i++) acc[i] = 0.f;

    // global key (position 0)
    if (mask[(size_t)b * S_] != 0) {
        const float* kp = k + (size_t)b * S_ * D_ + hh * HD_ + half * 32;
        const float* vp = v + (size_t)b * S_ * D_ + hh * HD_ + half * 32;
        float s = 0.f;
#pragma unroll
        for (int i = 0; i < 32; i++) s = fmaf(qr[i], kp[i], s);
        s += __shfl_xor_sync(0xffffffffu, s, 1);
        m = s; l = 1.f;
#pragma unroll
        for (int i = 0; i < 32; i++) acc[i] = vp[i];
    }

    for (int t = 0; t < 6; t++) {
        __syncthreads();
#pragma unroll
        for (int e = 0; e < 4; e++) {
            int id = tid + e * 256;            // 0..1023
            int r = id >> 4, c4 = id & 15;
            int d = c4 * 4;
            int col = d + (d >= 32 ? 4 : 0);
            int p = c * W_ - W_ + t * 64 + r;
            float4 kv = make_float4(0.f, 0.f, 0.f, 0.f), vv = kv;
            if (p >= 0 && p < S_) {
                size_t off = ((size_t)b * S_ + p) * D_ + hh * HD_ + d;
                kv = *(const float4*)(k + off);
                vv = *(const float4*)(v + off);
            }
            *(float4*)&ks[r][col] = kv;
            *(float4*)&vs[r][col] = vv;
        }
        if (tid < 64) {
            int p = c * W_ - W_ + t * 64 + tid;
            vld[tid] = (p >= 0 && p < S_) ? (mask[(size_t)b * S_ + p] != 0) : 0;
        }
        __syncthreads();
#pragma unroll 1
        for (int jc = 0; jc < 8; jc++) {
            float sv[8];
#pragma unroll
            for (int u = 0; u < 8; u++) {
                int jj = jc * 8 + u;
                const float* kb_ = &ks[jj][hoff];
                float s = 0.f;
#pragma unroll
                for (int i = 0; i < 8; i++) {
                    float4 k4 = *(const float4*)(kb_ + i * 4);
                    s = fmaf(qr[i*4], k4.x, s);   s = fmaf(qr[i*4+1], k4.y, s);
                    s = fmaf(qr[i*4+2], k4.z, s); s = fmaf(qr[i*4+3], k4.w, s);
                }
                s += __shfl_xor_sync(0xffffffffu, s, 1);
                int j = t * 64 + jj;
                bool ok = (j >= qi) && (j <= qi + 2 * W_) && vld[jj];
                sv[u] = ok ? s : -1e30f;
            }
            float mc = sv[0];
#pragma unroll
            for (int u = 1; u < 8; u++) mc = fmaxf(mc, sv[u]);
            float nm = fmaxf(m, mc);
            float corr = __expf(m - nm);
            l *= corr; m = nm;
#pragma unroll
            for (int i = 0; i < 32; i++) acc[i] *= corr;
#pragma unroll
            for (int u = 0; u < 8; u++) {
                float w = (sv[u] > -1e29f) ? __expf(sv[u] - m) : 0.f;
                l += w;
                const float* vb_ = &vs[jc * 8 + u][hoff];
#pragma unroll
                for (int i = 0; i < 8; i++) {
                    float4 v4 = *(const float4*)(vb_ + i * 4);
                    acc[i*4]   = fmaf(w, v4.x, acc[i*4]);
                    acc[i*4+1] = fmaf(w, v4.y, acc[i*4+1]);
                    acc[i*4+2] = fmaf(w, v4.z, acc[i*4+2]);
                    acc[i*4+3] = fmaf(w, v4.w, acc[i*4+3]);
                }
            }
        }
    }
    float inv = 1.f / l;
#pragma unroll
    for (int i = 0; i < 8; i++) {
        float4 o4 = make_float4(acc[i*4] * inv, acc[i*4+1] * inv,
                                acc[i*4+2] * inv, acc[i*4+3] * inv);
        *(float4*)(out + qoff + i * 4) = o4;
    }
}

// ---------------- global-token attention -> overwrite out row 0 ----------------
__global__ void __launch_bounds__(256) gattn_kernel(
    const float* __restrict__ qg, const float* __restrict__ kg,
    const float* __restrict__ vg, const int* __restrict__ mask,
    float* __restrict__ out) {
    const int hh = blockIdx.x, b = blockIdx.y;
    const int tid = threadIdx.x;
    __shared__ float sc[S_];
    __shared__ float qs[HD_];
    __shared__ float r1[8];
    __shared__ float stat[2];
    __shared__ float accb[4][HD_];
    if (tid < HD_) qs[tid] = qg[b * D_ + hh * HD_ + tid];
    __syncthreads();
    float lmax = -3.4e38f;
    for (int s = tid; s < S_; s += 256) {
        const float4* kr = (const float4*)(kg + ((size_t)b * S_ + s) * D_ + hh * HD_);
        float dot = 0.f;
#pragma unroll
        for (int i = 0; i < 16; i++) {
            float4 k4 = kr[i];
            dot = fmaf(qs[i*4], k4.x, dot);   dot = fmaf(qs[i*4+1], k4.y, dot);
            dot = fmaf(qs[i*4+2], k4.z, dot); dot = fmaf(qs[i*4+3], k4.w, dot);
        }
        if (mask[(size_t)b * S_ + s] == 0) dot = -1e9f;
        sc[s] = dot;
        lmax = fmaxf(lmax, dot);
    }
    {
        int lane = tid & 31, wid = tid >> 5;
#pragma unroll
        for (int o = 16; o > 0; o >>= 1) lmax = fmaxf(lmax, __shfl_down_sync(0xffffffffu, lmax, o));
        if (lane == 0) r1[wid] = lmax;
        __syncthreads();
        if (tid == 0) {
            float m2 = r1[0];
            for (int i = 1; i < 8; i++) m2 = fmaxf(m2, r1[i]);
            stat[0] = m2;
        }
        __syncthreads();
    }
    float gmax = stat[0];
    float lsum = 0.f;
    for (int s = tid; s < S_; s += 256) {
        float e = __expf(sc[s] - gmax);
        sc[s] = e;
        lsum += e;
    }
    {
        int lane = tid & 31, wid = tid >> 5;
#pragma unroll
        for (int o = 16; o > 0; o >>= 1) lsum += __shfl_down_sync(0xffffffffu, lsum, o);
        if (lane == 0) r1[wid] = lsum;
        __syncthreads();
        if (tid == 0) {
            float s2 = 0.f;
            for (int i = 0; i < 8; i++) s2 += r1[i];
            stat[1] = s2;
        }
        __syncthreads();
    }
    float inv = 1.f / stat[1];
    // parallel PV: 4 s-partitions x 64 d
    int d = tid & 63, part = tid >> 6;
    float a = 0.f;
    for (int s = part; s < S_; s += 4)
        a = fmaf(sc[s], vg[((size_t)b * S_ + s) * D_ + hh * HD_ + d], a);
    accb[part][d] = a;
    __syncthreads();
    if (tid < HD_)
        out[(size_t)b * S_ * D_ + hh * HD_ + tid] =
            (accb[0][tid] + accb[1][tid] + accb[2][tid] + accb[3][tid]) * inv;
}

// ---------------- classifier head ----------------
__global__ void cls_kernel(const float* __restrict__ h, const float* __restrict__ Wcls,
                           const float* __restrict__ bcls, const int* __restrict__ mask,
                           float* __restrict__ out) {
    int w = threadIdx.x >> 5, lane = threadIdx.x & 31;
    int b = w & 1, j = w >> 1;
    float s = 0.f;
    for (int kk = lane; kk < D_; kk += 32)
        s = fmaf(h[(size_t)b * S_ * D_ + kk], Wcls[kk * 3 + j], s);
#pragma unroll
    for (int o = 16; o > 0; o >>= 1) s += __shfl_down_sync(0xffffffffu, s, o);
    if (lane == 0) out[j * 2 + b] = 1.f / (1.f + expf(-(s + bcls[j])));
    if (threadIdx.x < 2) out[6 + threadIdx.x] = (float)mask[(size_t)threadIdx.x * S_];
}

// ---------------- launch ----------------
extern "C" void kernel_launch(void* const* d_in, const int* in_sizes, int n_in,
                              void* d_out, int out_size) {
    const int*   src  = (const int*)d_in[0];
    const int*   mask = (const int*)d_in[1];
    const float* etok = (const float*)d_in[3];
    const float* epos = (const float*)d_in[4];
    const float* elns = (const float*)d_in[5];
    const float* elnb = (const float*)d_in[6];
    const float* Wq   = (const float*)d_in[7];   const float* bq_p  = (const float*)d_in[8];
    const float* Wk   = (const float*)d_in[9];   const float* bk_p  = (const float*)d_in[10];
    const float* Wv   = (const float*)d_in[11];  const float* bv_p  = (const float*)d_in[12];
    const float* Wo   = (const float*)d_in[13];  const float* bo_p  = (const float*)d_in[14];
    const float* Wqg  = (const float*)d_in[15];  const float* bqg_p = (const float*)d_in[16];
    const float* Wkg  = (const float*)d_in[17];  const float* bkg_p = (const float*)d_in[18];
    const float* Wvg  = (const float*)d_in[19];  const float* bvg_p = (const float*)d_in[20];
    const float* ln1s = (const float*)d_in[21];  const float* ln1b  = (const float*)d_in[22];
    const float* W1   = (const float*)d_in[23];  const float* b1_p  = (const float*)d_in[24];
    const float* W2   = (const float*)d_in[25];  const float* b2_p  = (const float*)d_in[26];
    const float* ln2s = (const float*)d_in[27];  const float* ln2b  = (const float*)d_in[28];
    const float* Wcls = (const float*)d_in[29];  const float* bcls  = (const float*)d_in[30];
    float* out = (float*)d_out;

    float *ph, *pq, *pk, *pv, *pkg, *pvg, *pa, *pt, *pf, *pqg;
    cudaGetSymbolAddress((void**)&ph,  g_h);
    cudaGetSymbolAddress((void**)&pq,  g_q);
    cudaGetSymbolAddress((void**)&pk,  g_k);
    cudaGetSymbolAddress((void**)&pv,  g_v);
    cudaGetSymbolAddress((void**)&pkg, g_kg);
    cudaGetSymbolAddress((void**)&pvg, g_vg);
    cudaGetSymbolAddress((void**)&pa,  g_a);
    cudaGetSymbolAddress((void**)&pt,  g_t);
    cudaGetSymbolAddress((void**)&pf,  g_ff);
    cudaGetSymbolAddress((void**)&pqg, g_qg);

    const int M = B_ * S_;   // 4096

    embed_ln_kernel<<<M, 256>>>(src, etok, epos, elns, elnb, ph);

    for (int l = 0; l < L_; l++) {
        size_t wo  = (size_t)l * D_ * D_;
        size_t bof = (size_t)l * D_;

        ProjParams pp;
        pp.W[0] = Wq  + wo; pp.b[0] = bq_p  + bof; pp.o[0] = pq;  pp.alpha[0] = 0.125f;
        pp.W[1] = Wk  + wo; pp.b[1] = bk_p  + bof; pp.o[1] = pk;  pp.alpha[1] = 1.f;
        pp.W[2] = Wv  + wo; pp.b[2] = bv_p  + bof; pp.o[2] = pv;  pp.alpha[2] = 1.f;
        pp.W[3] = Wkg + wo; pp.b[3] = bkg_p + bof; pp.o[3] = pkg; pp.alpha[3] = 1.f;
        pp.W[4] = Wvg + wo; pp.b[4] = bvg_p + bof; pp.o[4] = pvg; pp.alpha[4] = 1.f;
        proj_gemm_kernel<<<dim3(D_ / 128, M / 128, 5), 256>>>(ph, pp, M, D_, D_);

        qg_kernel<<<dim3(B_, 3), 256>>>(ph, Wqg + wo, bqg_p + bof, pqg);
        attn_kernel<<<dim3(NC_, H_, B_), 256>>>(pq, pk, pv, mask, pa);
        gattn_kernel<<<dim3(H_, B_), 256>>>(pqg, pkg, pvg, mask, pa);

        tgemm_kernel<0><<<dim3(D_ / 128, M / 128), 256>>>(pa, Wo + wo, bo_p + bof, pt, M, D_, D_, 1.f);
        add_ln_kernel<<<M, 256>>>(ph, pt, ln1s + bof, ln1b + bof);
        tgemm_kernel<1><<<dim3(FF_ / 128, M / 128), 256>>>(ph, W1 + (size_t)l * D_ * FF_,
                                                           b1_p + (size_t)l * FF_, pf, M, FF_, D_, 1.f);
        tgemm_kernel<0><<<dim3(D_ / 128, M / 128), 256>>>(pf, W2 + (size_t)l * FF_ * D_,
                                                          b2_p + bof, pt, M, D_, FF_, 1.f);
        add_ln_kernel<<<M, 256>>>(ph, pt, ln2s + bof, ln2b + bof);
    }

    cls_kernel<<<1, 192>>>(ph, Wcls, bcls, mask, out);
}

// round 4
// speedup vs baseline: 2.9821x; 1.2034x over previous
#include <cuda_runtime.h>
#include <math.h>
#include <stdint.h>

#define B_  2
#define S_  2048
#define D_  768
#define H_  12
#define HD_ 64
#define L_  4
#define FF_ 3072
#define NC_ 16
#define W_  128

// ---------------- scratch (static device arrays; no allocation) ----------------
__device__ float g_h [B_*S_*D_];
__device__ float g_q [B_*S_*D_];
__device__ float g_k [B_*S_*D_];
__device__ float g_v [B_*S_*D_];
__device__ float g_kg[B_*S_*D_];
__device__ float g_vg[B_*S_*D_];
__device__ float g_a [B_*S_*D_];
__device__ float g_t [B_*S_*D_];
__device__ float g_ff[B_*S_*FF_];
__device__ float g_qg[B_*D_];

// ---------------- helpers ----------------
__device__ __forceinline__ uint32_t smem_u32(const void* p) {
    return (uint32_t)__cvta_generic_to_shared(p);
}
__device__ __forceinline__ void cp16(uint32_t dst, const void* src) {
    asm volatile("cp.async.cg.shared.global [%0], [%1], 16;" :: "r"(dst), "l"(src));
}
__device__ __forceinline__ void cp_commit() { asm volatile("cp.async.commit_group;"); }
template <int N> __device__ __forceinline__ void cp_wait() {
    asm volatile("cp.async.wait_group %0;" :: "n"(N));
}

__device__ __forceinline__ void mma_tf32(float* c, const unsigned* a, const unsigned* b) {
    asm volatile(
        "mma.sync.aligned.m16n8k8.row.col.f32.tf32.tf32.f32 "
        "{%0,%1,%2,%3}, {%4,%5,%6,%7}, {%8,%9}, {%0,%1,%2,%3};"
        : "+f"(c[0]), "+f"(c[1]), "+f"(c[2]), "+f"(c[3])
        : "r"(a[0]), "r"(a[1]), "r"(a[2]), "r"(a[3]), "r"(b[0]), "r"(b[1]));
}

__device__ __forceinline__ void block_reduce2(float a, float b, float* out2) {
    __shared__ float r1[8], r2[8];
    int lane = threadIdx.x & 31, wid = threadIdx.x >> 5;
#pragma unroll
    for (int o = 16; o > 0; o >>= 1) {
        a += __shfl_down_sync(0xffffffffu, a, o);
        b += __shfl_down_sync(0xffffffffu, b, o);
    }
    if (lane == 0) { r1[wid] = a; r2[wid] = b; }
    __syncthreads();
    if (wid == 0) {
        int nw = blockDim.x >> 5;
        a = (lane < nw) ? r1[lane] : 0.f;
        b = (lane < nw) ? r2[lane] : 0.f;
#pragma unroll
        for (int o = 4; o > 0; o >>= 1) {
            a += __shfl_down_sync(0xffffffffu, a, o);
            b += __shfl_down_sync(0xffffffffu, b, o);
        }
        if (lane == 0) { out2[0] = a; out2[1] = b; }
    }
    __syncthreads();
}

// ---------------- tf32 tensor-core GEMM, 3-stage cp.async, warp tile 64x64 ------
// C = act((A@B + bias) * alpha); A: MxK rm, B: KxN rm. M%128==N%128==K%16==0.
// Block 128x128x16, 128 thr, 4 warps in 2x2 (warp tile 64x64). Raw fp32 bits into
// mma.tf32 (hw truncates). A smem stride 16 w/ XOR swizzle; B smem stride 136.
template <int ACT>
__device__ __forceinline__ void gemm_core(
    const float* __restrict__ A, const float* __restrict__ Bm,
    const float* __restrict__ bias, float* __restrict__ C,
    int M, int N, int K, float alpha) {
    constexpr int AST = 128 * 16;      // u32 per A stage
    constexpr int BST = 16 * 136;      // u32 per B stage
    __shared__ uint32_t As[3 * AST];
    __shared__ uint32_t Bs[3 * BST];

    const int tid = threadIdx.x, lane = tid & 31, wid = tid >> 5;
    const int wm = (wid >> 1) * 64, wn = (wid & 1) * 64;
    const int g = lane >> 2, t = lane & 3;
    const int bm = blockIdx.y * 128, bn = blockIdx.x * 128;

    // per-thread load slots: 4 chunks of A (128x4 float4), 4 of B (16x32 float4)
    int arow[4], ac4[4], brow[4], bc4[4];
    uint32_t aBase[4], bBase[4];
#pragma unroll
    for (int i = 0; i < 4; i++) {
        int f = tid + i * 128;
        arow[i] = f >> 2;  ac4[i] = f & 3;
        brow[i] = f >> 5;  bc4[i] = f & 31;
        aBase[i] = smem_u32(&As[arow[i] * 16 + (ac4[i] ^ (arow[i] & 3)) * 4]);
        bBase[i] = smem_u32(&Bs[brow[i] * 136 + bc4[i] * 4]);
    }

    float acc[4][8][4];
#pragma unroll
    for (int i = 0; i < 4; i++)
#pragma unroll
        for (int j = 0; j < 8; j++)
#pragma unroll
            for (int r = 0; r < 4; r++) acc[i][j][r] = 0.f;

    const int nk = K >> 4;

    auto issue = [&](int kt) {
        const int s = kt % 3;
        const int k0 = kt << 4;
#pragma unroll
        for (int i = 0; i < 4; i++) {
            cp16(aBase[i] + s * (AST * 4),
                 A + (size_t)(bm + arow[i]) * K + k0 + ac4[i] * 4);
            cp16(bBase[i] + s * (BST * 4),
                 Bm + (size_t)(k0 + brow[i]) * N + bn + bc4[i] * 4);
        }
        cp_commit();
    };

    issue(0);
    if (nk > 1) issue(1);

    for (int kt = 0; kt < nk; kt++) {
        if (kt + 1 == nk) cp_wait<0>(); else cp_wait<1>();
        __syncthreads();
        if (kt + 2 < nk) issue(kt + 2);

        const uint32_t* sA = &As[(kt % 3) * AST];
        const uint32_t* sB = &Bs[(kt % 3) * BST];
        const int xo = (g & 3) << 2;
#pragma unroll
        for (int kb = 0; kb < 16; kb += 8) {
            const int k0x = (kb + t) ^ xo;
            const int k1x = (kb + t + 4) ^ xo;
            unsigned af[4][4], bf[8][2];
#pragma unroll
            for (int mt = 0; mt < 4; mt++) {
                int r = wm + mt * 16 + g;
                af[mt][0] = sA[r * 16 + k0x];
                af[mt][1] = sA[(r + 8) * 16 + k0x];
                af[mt][2] = sA[r * 16 + k1x];
                af[mt][3] = sA[(r + 8) * 16 + k1x];
            }
#pragma unroll
            for (int nt = 0; nt < 8; nt++) {
                int cc = wn + nt * 8 + g;
                bf[nt][0] = sB[(kb + t) * 136 + cc];
                bf[nt][1] = sB[(kb + t + 4) * 136 + cc];
            }
#pragma unroll
            for (int mt = 0; mt < 4; mt++)
#pragma unroll
                for (int nt = 0; nt < 8; nt++)
                    mma_tf32(acc[mt][nt], af[mt], bf[nt]);
        }
        __syncthreads();
    }

    // epilogue
#pragma unroll
    for (int mt = 0; mt < 4; mt++) {
#pragma unroll
        for (int nt = 0; nt < 8; nt++) {
            int r0 = bm + wm + mt * 16 + g;
            int c0 = bn + wn + nt * 8 + t * 2;
            float b0 = bias[c0], b1 = bias[c0 + 1];
            float v[4];
            v[0] = (acc[mt][nt][0] + b0) * alpha;
            v[1] = (acc[mt][nt][1] + b1) * alpha;
            v[2] = (acc[mt][nt][2] + b0) * alpha;
            v[3] = (acc[mt][nt][3] + b1) * alpha;
            if (ACT == 1) {
#pragma unroll
                for (int i = 0; i < 4; i++)
                    v[i] = 0.5f * v[i] * (1.f + erff(v[i] * 0.7071067811865476f));
            }
            *(float2*)(C + (size_t)r0 * N + c0)       = make_float2(v[0], v[1]);
            *(float2*)(C + (size_t)(r0 + 8) * N + c0) = make_float2(v[2], v[3]);
        }
    }
}

template <int ACT>
__global__ void __launch_bounds__(128, 2) tgemm_kernel(
    const float* __restrict__ A, const float* __restrict__ Bm,
    const float* __restrict__ bias, float* __restrict__ C,
    int M, int N, int K, float alpha) {
    gemm_core<ACT>(A, Bm, bias, C, M, N, K, alpha);
}

struct ProjParams {
    const float* W[5];
    const float* b[5];
    float*       o[5];
    float        alpha[5];
};

__global__ void __launch_bounds__(128, 2) proj_gemm_kernel(
    const float* __restrict__ A, ProjParams p, int M, int N, int K) {
    int z = blockIdx.z;
    gemm_core<0>(A, p.W[z], p.b[z], p.o[z], M, N, K, p.alpha[z]);
}

// ---------------- embedding + LN ----------------
__global__ void embed_ln_kernel(const int* __restrict__ src,
                                const float* __restrict__ etok,
                                const float* __restrict__ epos,
                                const float* __restrict__ gs,
                                const float* __restrict__ gb,
                                float* __restrict__ h) {
    int tok = blockIdx.x;
    int s   = tok & (S_ - 1);
    int tid = threadIdx.x;
    __shared__ float stat[2];
    size_t row = (size_t)src[tok] * D_;
    float vals[3]; float sum = 0.f, sq = 0.f;
#pragma unroll
    for (int i = 0; i < 3; i++) {
        int d = tid + i * 256;
        float v = etok[row + d] + epos[(size_t)s * D_ + d];
        vals[i] = v; sum += v; sq += v * v;
    }
    block_reduce2(sum, sq, stat);
    float mean = stat[0] * (1.f / D_);
    float var  = stat[1] * (1.f / D_) - mean * mean;
    float inv  = 1.f / sqrtf(var + 1e-5f);
#pragma unroll
    for (int i = 0; i < 3; i++) {
        int d = tid + i * 256;
        h[(size_t)tok * D_ + d] = (vals[i] - mean) * inv * gs[d] + gb[d];
    }
}

// ---------------- residual add + LN (in place on h) ----------------
__global__ void add_ln_kernel(float* __restrict__ h, const float* __restrict__ x,
                              const float* __restrict__ sc, const float* __restrict__ bi) {
    int tok = blockIdx.x;
    int tid = threadIdx.x;
    __shared__ float stat[2];
    float* hp = h + (size_t)tok * D_;
    const float* xp = x + (size_t)tok * D_;
    float vals[3]; float sum = 0.f, sq = 0.f;
#pragma unroll
    for (int i = 0; i < 3; i++) {
        int d = tid + i * 256;
        float v = hp[d] + xp[d];
        vals[i] = v; sum += v; sq += v * v;
    }
    block_reduce2(sum, sq, stat);
    float mean = stat[0] * (1.f / D_);
    float var  = stat[1] * (1.f / D_) - mean * mean;
    float inv  = 1.f / sqrtf(var + 1e-5f);
#pragma unroll
    for (int i = 0; i < 3; i++) {
        int d = tid + i * 256;
        hp[d] = (vals[i] - mean) * inv * sc[d] + bi[d];
    }
}

// ---------------- qg = (h[:,0,:] @ Wqg + bqg) / 8 ----------------
__global__ void qg_kernel(const float* __restrict__ h, const float* __restrict__ Wm,
                          const float* __restrict__ bias, float* __restrict__ qg) {
    int b = blockIdx.x;
    int j = blockIdx.y * 256 + threadIdx.x;
    __shared__ float hs[D_];
    for (int i = threadIdx.x; i < D_; i += 256) hs[i] = h[(size_t)b * S_ * D_ + i];
    __syncthreads();
    float s = 0.f;
    for (int kk = 0; kk < D_; kk++) s = fmaf(hs[kk], Wm[(size_t)kk * D_ + j], s);
    qg[b * D_ + j] = (s + bias[j]) * 0.125f;
}

// ---------------- sliding-window + global-key attention ----------------
__global__ void __launch_bounds__(256, 2) attn_kernel(
    const float* __restrict__ q, const float* __restrict__ k, const float* __restrict__ v,
    const int* __restrict__ mask, float* __restrict__ out) {
    const int c = blockIdx.x, hh = blockIdx.y, b = blockIdx.z;
    const int tid = threadIdx.x;
    const int qi = tid >> 1, half = tid & 1;
    __shared__ float ks[64][72];
    __shared__ float vs[64][72];
    __shared__ int vld[64];
    const int hoff = half * 36;
    const size_t qoff = ((size_t)b * S_ + c * W_ + qi) * D_ + hh * HD_ + half * 32;
    float qr[32], acc[32];
#pragma unroll
    for (int i = 0; i < 8; i++) {
        float4 t4 = *(const float4*)(q + qoff + i * 4);
        qr[i*4] = t4.x; qr[i*4+1] = t4.y; qr[i*4+2] = t4.z; qr[i*4+3] = t4.w;
    }
    float m = -1e30f, l = 0.f;
#pragma unroll
    for (int i = 0; i < 32; i++) acc[i] = 0.f;

    if (mask[(size_t)b * S_] != 0) {
        const float* kp = k + (size_t)b * S_ * D_ + hh * HD_ + half * 32;
        const float* vp = v + (size_t)b * S_ * D_ + hh * HD_ + half * 32;
        float s = 0.f;
#pragma unroll
        for (int i = 0; i < 32; i++) s = fmaf(qr[i], kp[i], s);
        s += __shfl_xor_sync(0xffffffffu, s, 1);
        m = s; l = 1.f;
#pragma unroll
        for (int i = 0; i < 32; i++) acc[i] = vp[i];
    }

    for (int t = 0; t < 6; t++) {
        __syncthreads();
#pragma unroll
        for (int e = 0; e < 4; e++) {
            int id = tid + e * 256;
            int r = id >> 4, c4 = id & 15;
            int d = c4 * 4;
            int col = d + (d >= 32 ? 4 : 0);
            int p = c * W_ - W_ + t * 64 + r;
            float4 kv = make_float4(0.f, 0.f, 0.f, 0.f), vv = kv;
            if (p >= 0 && p < S_) {
                size_t off = ((size_t)b * S_ + p) * D_ + hh * HD_ + d;
                kv = *(const float4*)(k + off);
                vv = *(const float4*)(v + off);
            }
            *(float4*)&ks[r][col] = kv;
            *(float4*)&vs[r][col] = vv;
        }
        if (tid < 64) {
            int p = c * W_ - W_ + t * 64 + tid;
            vld[tid] = (p >= 0 && p < S_) ? (mask[(size_t)b * S_ + p] != 0) : 0;
        }
        __syncthreads();
#pragma unroll 1
        for (int jc = 0; jc < 8; jc++) {
            float sv[8];
#pragma unroll
            for (int u = 0; u < 8; u++) {
                int jj = jc * 8 + u;
                const float* kb_ = &ks[jj][hoff];
                float s = 0.f;
#pragma unroll
                for (int i = 0; i < 8; i++) {
                    float4 k4 = *(const float4*)(kb_ + i * 4);
                    s = fmaf(qr[i*4], k4.x, s);   s = fmaf(qr[i*4+1], k4.y, s);
                    s = fmaf(qr[i*4+2], k4.z, s); s = fmaf(qr[i*4+3], k4.w, s);
                }
                s += __shfl_xor_sync(0xffffffffu, s, 1);
                int j = t * 64 + jj;
                bool ok = (j >= qi) && (j <= qi + 2 * W_) && vld[jj];
                sv[u] = ok ? s : -1e30f;
            }
            float mc = sv[0];
#pragma unroll
            for (int u = 1; u < 8; u++) mc = fmaxf(mc, sv[u]);
            float nm = fmaxf(m, mc);
            float corr = __expf(m - nm);
            l *= corr; m = nm;
#pragma unroll
            for (int i = 0; i < 32; i++) acc[i] *= corr;
#pragma unroll
            for (int u = 0; u < 8; u++) {
                float w = (sv[u] > -1e29f) ? __expf(sv[u] - m) : 0.f;
                l += w;
                const float* vb_ = &vs[jc * 8 + u][hoff];
#pragma unroll
                for (int i = 0; i < 8; i++) {
                    float4 v4 = *(const float4*)(vb_ + i * 4);
                    acc[i*4]   = fmaf(w, v4.x, acc[i*4]);
                    acc[i*4+1] = fmaf(w, v4.y, acc[i*4+1]);
                    acc[i*4+2] = fmaf(w, v4.z, acc[i*4+2]);
                    acc[i*4+3] = fmaf(w, v4.w, acc[i*4+3]);
                }
            }
        }
    }
    float inv = 1.f / l;
#pragma unroll
    for (int i = 0; i < 8; i++) {
        float4 o4 = make_float4(acc[i*4] * inv, acc[i*4+1] * inv,
                                acc[i*4+2] * inv, acc[i*4+3] * inv);
        *(float4*)(out + qoff + i * 4) = o4;
    }
}

// ---------------- global-token attention -> overwrite out row 0 ----------------
__global__ void __launch_bounds__(256) gattn_kernel(
    const float* __restrict__ qg, const float* __restrict__ kg,
    const float* __restrict__ vg, const int* __restrict__ mask,
    float* __restrict__ out) {
    const int hh = blockIdx.x, b = blockIdx.y;
    const int tid = threadIdx.x;
    __shared__ float sc[S_];
    __shared__ float qs[HD_];
    __shared__ float r1[8];
    __shared__ float stat[2];
    __shared__ float accb[4][HD_];
    if (tid < HD_) qs[tid] = qg[b * D_ + hh * HD_ + tid];
    __syncthreads();
    float lmax = -3.4e38f;
    for (int s = tid; s < S_; s += 256) {
        const float4* kr = (const float4*)(kg + ((size_t)b * S_ + s) * D_ + hh * HD_);
        float dot = 0.f;
#pragma unroll
        for (int i = 0; i < 16; i++) {
            float4 k4 = kr[i];
            dot = fmaf(qs[i*4], k4.x, dot);   dot = fmaf(qs[i*4+1], k4.y, dot);
            dot = fmaf(qs[i*4+2], k4.z, dot); dot = fmaf(qs[i*4+3], k4.w, dot);
        }
        if (mask[(size_t)b * S_ + s] == 0) dot = -1e9f;
        sc[s] = dot;
        lmax = fmaxf(lmax, dot);
    }
    {
        int lane = tid & 31, wid = tid >> 5;
#pragma unroll
        for (int o = 16; o > 0; o >>= 1) lmax = fmaxf(lmax, __shfl_down_sync(0xffffffffu, lmax, o));
        if (lane == 0) r1[wid] = lmax;
        __syncthreads();
        if (tid == 0) {
            float m2 = r1[0];
            for (int i = 1; i < 8; i++) m2 = fmaxf(m2, r1[i]);
            stat[0] = m2;
        }
        __syncthreads();
    }
    float gmax = stat[0];
    float lsum = 0.f;
    for (int s = tid; s < S_; s += 256) {
        float e = __expf(sc[s] - gmax);
        sc[s] = e;
        lsum += e;
    }
    {
        int lane = tid & 31, wid = tid >> 5;
#pragma unroll
        for (int o = 16; o > 0; o >>= 1) lsum += __shfl_down_sync(0xffffffffu, lsum, o);
        if (lane == 0) r1[wid] = lsum;
        __syncthreads();
        if (tid == 0) {
            float s2 = 0.f;
            for (int i = 0; i < 8; i++) s2 += r1[i];
            stat[1] = s2;
        }
        __syncthreads();
    }
    float inv = 1.f / stat[1];
    int d = tid & 63, part = tid >> 6;
    float a = 0.f;
    for (int s = part; s < S_; s += 4)
        a = fmaf(sc[s], vg[((size_t)b * S_ + s) * D_ + hh * HD_ + d], a);
    accb[part][d] = a;
    __syncthreads();
    if (tid < HD_)
        out[(size_t)b * S_ * D_ + hh * HD_ + tid] =
            (accb[0][tid] + accb[1][tid] + accb[2][tid] + accb[3][tid]) * inv;
}

// ---------------- classifier head ----------------
__global__ void cls_kernel(const float* __restrict__ h, const float* __restrict__ Wcls,
                           const float* __restrict__ bcls, const int* __restrict__ mask,
                           float* __restrict__ out) {
    int w = threadIdx.x >> 5, lane = threadIdx.x & 31;
    int b = w & 1, j = w >> 1;
    float s = 0.f;
    for (int kk = lane; kk < D_; kk += 32)
        s = fmaf(h[(size_t)b * S_ * D_ + kk], Wcls[kk * 3 + j], s);
#pragma unroll
    for (int o = 16; o > 0; o >>= 1) s += __shfl_down_sync(0xffffffffu, s, o);
    if (lane == 0) out[j * 2 + b] = 1.f / (1.f + expf(-(s + bcls[j])));
    if (threadIdx.x < 2) out[6 + threadIdx.x] = (float)mask[(size_t)threadIdx.x * S_];
}

// ---------------- launch ----------------
extern "C" void kernel_launch(void* const* d_in, const int* in_sizes, int n_in,
                              void* d_out, int out_size) {
    const int*   src  = (const int*)d_in[0];
    const int*   mask = (const int*)d_in[1];
    const float* etok = (const float*)d_in[3];
    const float* epos = (const float*)d_in[4];
    const float* elns = (const float*)d_in[5];
    const float* elnb = (const float*)d_in[6];
    const float* Wq   = (const float*)d_in[7];   const float* bq_p  = (const float*)d_in[8];
    const float* Wk   = (const float*)d_in[9];   const float* bk_p  = (const float*)d_in[10];
    const float* Wv   = (const float*)d_in[11];  const float* bv_p  = (const float*)d_in[12];
    const float* Wo   = (const float*)d_in[13];  const float* bo_p  = (const float*)d_in[14];
    const float* Wqg  = (const float*)d_in[15];  const float* bqg_p = (const float*)d_in[16];
    const float* Wkg  = (const float*)d_in[17];  const float* bkg_p = (const float*)d_in[18];
    const float* Wvg  = (const float*)d_in[19];  const float* bvg_p = (const float*)d_in[20];
    const float* ln1s = (const float*)d_in[21];  const float* ln1b  = (const float*)d_in[22];
    const float* W1   = (const float*)d_in[23];  const float* b1_p  = (const float*)d_in[24];
    const float* W2   = (const float*)d_in[25];  const float* b2_p  = (const float*)d_in[26];
    const float* ln2s = (const float*)d_in[27];  const float* ln2b  = (const float*)d_in[28];
    const float* Wcls = (const float*)d_in[29];  const float* bcls  = (const float*)d_in[30];
    float* out = (float*)d_out;

    float *ph, *pq, *pk, *pv, *pkg, *pvg, *pa, *pt, *pf, *pqg;
    cudaGetSymbolAddress((void**)&ph,  g_h);
    cudaGetSymbolAddress((void**)&pq,  g_q);
    cudaGetSymbolAddress((void**)&pk,  g_k);
    cudaGetSymbolAddress((void**)&pv,  g_v);
    cudaGetSymbolAddress((void**)&pkg, g_kg);
    cudaGetSymbolAddress((void**)&pvg, g_vg);
    cudaGetSymbolAddress((void**)&pa,  g_a);
    cudaGetSymbolAddress((void**)&pt,  g_t);
    cudaGetSymbolAddress((void**)&pf,  g_ff);
    cudaGetSymbolAddress((void**)&pqg, g_qg);

    const int M = B_ * S_;   // 4096

    embed_ln_kernel<<<M, 256>>>(src, etok, epos, elns, elnb, ph);

    for (int l = 0; l < L_; l++) {
        size_t wo  = (size_t)l * D_ * D_;
        size_t bof = (size_t)l * D_;

        ProjParams pp;
        pp.W[0] = Wq  + wo; pp.b[0] = bq_p  + bof; pp.o[0] = pq;  pp.alpha[0] = 0.125f;
        pp.W[1] = Wk  + wo; pp.b[1] = bk_p  + bof; pp.o[1] = pk;  pp.alpha[1] = 1.f;
        pp.W[2] = Wv  + wo; pp.b[2] = bv_p  + bof; pp.o[2] = pv;  pp.alpha[2] = 1.f;
        pp.W[3] = Wkg + wo; pp.b[3] = bkg_p + bof; pp.o[3] = pkg; pp.alpha[3] = 1.f;
        pp.W[4] = Wvg + wo; pp.b[4] = bvg_p + bof; pp.o[4] = pvg; pp.alpha[4] = 1.f;
        proj_gemm_kernel<<<dim3(D_ / 128, M / 128, 5), 128>>>(ph, pp, M, D_, D_);

        qg_kernel<<<dim3(B_, 3), 256>>>(ph, Wqg + wo, bqg_p + bof, pqg);
        attn_kernel<<<dim3(NC_, H_, B_), 256>>>(pq, pk, pv, mask, pa);
        gattn_kernel<<<dim3(H_, B_), 256>>>(pqg, pkg, pvg, mask, pa);

        tgemm_kernel<0><<<dim3(D_ / 128, M / 128), 128>>>(pa, Wo + wo, bo_p + bof, pt, M, D_, D_, 1.f);
        add_ln_kernel<<<M, 256>>>(ph, pt, ln1s + bof, ln1b + bof);
        tgemm_kernel<1><<<dim3(FF_ / 128, M / 128), 128>>>(ph, W1 + (size_t)l * D_ * FF_,
                                                           b1_p + (size_t)l * FF_, pf, M, FF_, D_, 1.f);
        tgemm_kernel<0><<<dim3(D_ / 128, M / 128), 128>>>(pf, W2 + (size_t)l * FF_ * D_,
                                                          b2_p + bof, pt, M, D_, FF_, 1.f);
        add_ln_kernel<<<M, 256>>>(ph, pt, ln2s + bof, ln2b + bof);
    }

    cls_kernel<<<1, 192>>>(ph, Wcls, bcls, mask, out);
}

// round 5
// speedup vs baseline: 3.4409x; 1.1539x over previous
#include <cuda_runtime.h>
#include <math.h>
#include <stdint.h>

#define B_  2
#define S_  2048
#define D_  768
#define H_  12
#define HD_ 64
#define L_  4
#define FF_ 3072
#define NC_ 16
#define W_  128

// ---------------- scratch (static device arrays; no allocation) ----------------
__device__ float g_h [B_*S_*D_];
__device__ float g_q [B_*S_*D_];
__device__ float g_k [B_*S_*D_];
__device__ float g_v [B_*S_*D_];
__device__ float g_kg[B_*S_*D_];
__device__ float g_vg[B_*S_*D_];
__device__ float g_a [B_*S_*D_];
__device__ float g_t [B_*S_*D_];
__device__ float g_ff[B_*S_*FF_];
__device__ float g_qg[B_*D_];

// ---------------- helpers ----------------
__device__ __forceinline__ uint32_t smem_u32(const void* p) {
    return (uint32_t)__cvta_generic_to_shared(p);
}
__device__ __forceinline__ void cp16(uint32_t dst, const void* src) {
    asm volatile("cp.async.cg.shared.global [%0], [%1], 16;" :: "r"(dst), "l"(src));
}
__device__ __forceinline__ void cp_commit() { asm volatile("cp.async.commit_group;"); }
template <int N> __device__ __forceinline__ void cp_wait() {
    asm volatile("cp.async.wait_group %0;" :: "n"(N));
}
__device__ __forceinline__ uint32_t f2tf(float x) {
    uint32_t r;
    asm("cvt.rna.tf32.f32 %0, %1;" : "=r"(r) : "f"(x));
    return r;
}

__device__ __forceinline__ void mma_tf32(float* c, const unsigned* a, const unsigned* b) {
    asm volatile(
        "mma.sync.aligned.m16n8k8.row.col.f32.tf32.tf32.f32 "
        "{%0,%1,%2,%3}, {%4,%5,%6,%7}, {%8,%9}, {%0,%1,%2,%3};"
        : "+f"(c[0]), "+f"(c[1]), "+f"(c[2]), "+f"(c[3])
        : "r"(a[0]), "r"(a[1]), "r"(a[2]), "r"(a[3]), "r"(b[0]), "r"(b[1]));
}

__device__ __forceinline__ void block_reduce2(float a, float b, float* out2) {
    __shared__ float r1[8], r2[8];
    int lane = threadIdx.x & 31, wid = threadIdx.x >> 5;
#pragma unroll
    for (int o = 16; o > 0; o >>= 1) {
        a += __shfl_down_sync(0xffffffffu, a, o);
        b += __shfl_down_sync(0xffffffffu, b, o);
    }
    if (lane == 0) { r1[wid] = a; r2[wid] = b; }
    __syncthreads();
    if (wid == 0) {
        int nw = blockDim.x >> 5;
        a = (lane < nw) ? r1[lane] : 0.f;
        b = (lane < nw) ? r2[lane] : 0.f;
#pragma unroll
        for (int o = 4; o > 0; o >>= 1) {
            a += __shfl_down_sync(0xffffffffu, a, o);
            b += __shfl_down_sync(0xffffffffu, b, o);
        }
        if (lane == 0) { out2[0] = a; out2[1] = b; }
    }
    __syncthreads();
}

// ---------------- tf32 tensor-core GEMM, 3-stage cp.async, warp tile 64x64 ------
template <int ACT>
__device__ __forceinline__ void gemm_core(
    const float* __restrict__ A, const float* __restrict__ Bm,
    const float* __restrict__ bias, float* __restrict__ C,
    int M, int N, int K, float alpha) {
    constexpr int AST = 128 * 16;
    constexpr int BST = 16 * 136;
    __shared__ uint32_t As[3 * AST];
    __shared__ uint32_t Bs[3 * BST];

    const int tid = threadIdx.x, lane = tid & 31, wid = tid >> 5;
    const int wm = (wid >> 1) * 64, wn = (wid & 1) * 64;
    const int g = lane >> 2, t = lane & 3;
    const int bm = blockIdx.y * 128, bn = blockIdx.x * 128;

    int arow[4], ac4[4], brow[4], bc4[4];
    uint32_t aBase[4], bBase[4];
#pragma unroll
    for (int i = 0; i < 4; i++) {
        int f = tid + i * 128;
        arow[i] = f >> 2;  ac4[i] = f & 3;
        brow[i] = f >> 5;  bc4[i] = f & 31;
        aBase[i] = smem_u32(&As[arow[i] * 16 + (ac4[i] ^ (arow[i] & 3)) * 4]);
        bBase[i] = smem_u32(&Bs[brow[i] * 136 + bc4[i] * 4]);
    }

    float acc[4][8][4];
#pragma unroll
    for (int i = 0; i < 4; i++)
#pragma unroll
        for (int j = 0; j < 8; j++)
#pragma unroll
            for (int r = 0; r < 4; r++) acc[i][j][r] = 0.f;

    const int nk = K >> 4;

    auto issue = [&](int kt) {
        const int s = kt % 3;
        const int k0 = kt << 4;
#pragma unroll
        for (int i = 0; i < 4; i++) {
            cp16(aBase[i] + s * (AST * 4),
                 A + (size_t)(bm + arow[i]) * K + k0 + ac4[i] * 4);
            cp16(bBase[i] + s * (BST * 4),
                 Bm + (size_t)(k0 + brow[i]) * N + bn + bc4[i] * 4);
        }
        cp_commit();
    };

    issue(0);
    if (nk > 1) issue(1);

    for (int kt = 0; kt < nk; kt++) {
        if (kt + 1 == nk) cp_wait<0>(); else cp_wait<1>();
        __syncthreads();
        if (kt + 2 < nk) issue(kt + 2);

        const uint32_t* sA = &As[(kt % 3) * AST];
        const uint32_t* sB = &Bs[(kt % 3) * BST];
        const int xo = (g & 3) << 2;
#pragma unroll
        for (int kb = 0; kb < 16; kb += 8) {
            const int k0x = (kb + t) ^ xo;
            const int k1x = (kb + t + 4) ^ xo;
            unsigned af[4][4], bf[8][2];
#pragma unroll
            for (int mt = 0; mt < 4; mt++) {
                int r = wm + mt * 16 + g;
                af[mt][0] = sA[r * 16 + k0x];
                af[mt][1] = sA[(r + 8) * 16 + k0x];
                af[mt][2] = sA[r * 16 + k1x];
                af[mt][3] = sA[(r + 8) * 16 + k1x];
            }
#pragma unroll
            for (int nt = 0; nt < 8; nt++) {
                int cc = wn + nt * 8 + g;
                bf[nt][0] = sB[(kb + t) * 136 + cc];
                bf[nt][1] = sB[(kb + t + 4) * 136 + cc];
            }
#pragma unroll
            for (int mt = 0; mt < 4; mt++)
#pragma unroll
                for (int nt = 0; nt < 8; nt++)
                    mma_tf32(acc[mt][nt], af[mt], bf[nt]);
        }
        __syncthreads();
    }

#pragma unroll
    for (int mt = 0; mt < 4; mt++) {
#pragma unroll
        for (int nt = 0; nt < 8; nt++) {
            int r0 = bm + wm + mt * 16 + g;
            int c0 = bn + wn + nt * 8 + t * 2;
            float b0 = bias[c0], b1 = bias[c0 + 1];
            float v[4];
            v[0] = (acc[mt][nt][0] + b0) * alpha;
            v[1] = (acc[mt][nt][1] + b1) * alpha;
            v[2] = (acc[mt][nt][2] + b0) * alpha;
            v[3] = (acc[mt][nt][3] + b1) * alpha;
            if (ACT == 1) {
#pragma unroll
                for (int i = 0; i < 4; i++)
                    v[i] = 0.5f * v[i] * (1.f + erff(v[i] * 0.7071067811865476f));
            }
            *(float2*)(C + (size_t)r0 * N + c0)       = make_float2(v[0], v[1]);
            *(float2*)(C + (size_t)(r0 + 8) * N + c0) = make_float2(v[2], v[3]);
        }
    }
}

template <int ACT>
__global__ void __launch_bounds__(128, 2) tgemm_kernel(
    const float* __restrict__ A, const float* __restrict__ Bm,
    const float* __restrict__ bias, float* __restrict__ C,
    int M, int N, int K, float alpha) {
    gemm_core<ACT>(A, Bm, bias, C, M, N, K, alpha);
}

struct ProjParams {
    const float* W[5];
    const float* b[5];
    float*       o[5];
    float        alpha[5];
};

__global__ void __launch_bounds__(128, 2) proj_gemm_kernel(
    const float* __restrict__ A, ProjParams p, int M, int N, int K) {
    int z = blockIdx.z;
    gemm_core<0>(A, p.W[z], p.b[z], p.o[z], M, N, K, p.alpha[z]);
}

// ---------------- embedding + LN ----------------
__global__ void embed_ln_kernel(const int* __restrict__ src,
                                const float* __restrict__ etok,
                                const float* __restrict__ epos,
                                const float* __restrict__ gs,
                                const float* __restrict__ gb,
                                float* __restrict__ h) {
    int tok = blockIdx.x;
    int s   = tok & (S_ - 1);
    int tid = threadIdx.x;
    __shared__ float stat[2];
    size_t row = (size_t)src[tok] * D_;
    float vals[3]; float sum = 0.f, sq = 0.f;
#pragma unroll
    for (int i = 0; i < 3; i++) {
        int d = tid + i * 256;
        float v = etok[row + d] + epos[(size_t)s * D_ + d];
        vals[i] = v; sum += v; sq += v * v;
    }
    block_reduce2(sum, sq, stat);
    float mean = stat[0] * (1.f / D_);
    float var  = stat[1] * (1.f / D_) - mean * mean;
    float inv  = 1.f / sqrtf(var + 1e-5f);
#pragma unroll
    for (int i = 0; i < 3; i++) {
        int d = tid + i * 256;
        h[(size_t)tok * D_ + d] = (vals[i] - mean) * inv * gs[d] + gb[d];
    }
}

// ---------------- residual add + LN (in place on h) ----------------
__global__ void add_ln_kernel(float* __restrict__ h, const float* __restrict__ x,
                              const float* __restrict__ sc, const float* __restrict__ bi) {
    int tok = blockIdx.x;
    int tid = threadIdx.x;
    __shared__ float stat[2];
    float* hp = h + (size_t)tok * D_;
    const float* xp = x + (size_t)tok * D_;
    float vals[3]; float sum = 0.f, sq = 0.f;
#pragma unroll
    for (int i = 0; i < 3; i++) {
        int d = tid + i * 256;
        float v = hp[d] + xp[d];
        vals[i] = v; sum += v; sq += v * v;
    }
    block_reduce2(sum, sq, stat);
    float mean = stat[0] * (1.f / D_);
    float var  = stat[1] * (1.f / D_) - mean * mean;
    float inv  = 1.f / sqrtf(var + 1e-5f);
#pragma unroll
    for (int i = 0; i < 3; i++) {
        int d = tid + i * 256;
        hp[d] = (vals[i] - mean) * inv * sc[d] + bi[d];
    }
}

// ---------------- qg = (h[:,0,:] @ Wqg + bqg) / 8 ----------------
__global__ void qg_kernel(const float* __restrict__ h, const float* __restrict__ Wm,
                          const float* __restrict__ bias, float* __restrict__ qg) {
    int b = blockIdx.x;
    int j = blockIdx.y * 256 + threadIdx.x;
    __shared__ float hs[D_];
    for (int i = threadIdx.x; i < D_; i += 256) hs[i] = h[(size_t)b * S_ * D_ + i];
    __syncthreads();
    float s = 0.f;
    for (int kk = 0; kk < D_; kk++) s = fmaf(hs[kk], Wm[(size_t)kk * D_ + j], s);
    qg[b * D_ + j] = (s + bias[j]) * 0.125f;
}

// ---------------- sliding-window + global-key attention (tensor-core flash) -----
// Block = (chunk, head, batch). 8 warps x 16 query rows. Q fragments in regs,
// QK^T and PV via mma.tf32; P stays in registers (C-frag -> A-frag quad shuffle).
__global__ void __launch_bounds__(256) attn_kernel(
    const float* __restrict__ q, const float* __restrict__ k, const float* __restrict__ v,
    const int* __restrict__ mask, float* __restrict__ out) {
    const int c = blockIdx.x, hh = blockIdx.y, b = blockIdx.z;
    const int tid = threadIdx.x, lane = tid & 31, wid = tid >> 5;
    const int g = lane >> 2, t = lane & 3;
    const int wq = wid * 16;
    __shared__ float Ks[64 * 68];
    __shared__ float Vs[64 * 72];
    __shared__ float k0s[64], v0s[64];
    __shared__ int vld[64];

    const size_t hb = (size_t)b * S_ * D_ + hh * HD_;

    if (tid < 64) { k0s[tid] = k[hb + tid]; v0s[tid] = v[hb + tid]; }

    // Q fragments (rna -> tf32), rows wq+g / wq+g+8
    uint32_t Qf[8][4];
    {
        const float* qr0 = q + hb + (size_t)(c * W_ + wq + g) * D_;
        const float* qr1 = qr0 + 8 * D_;
#pragma unroll
        for (int kk = 0; kk < 8; kk++) {
            Qf[kk][0] = f2tf(qr0[kk * 8 + t]);
            Qf[kk][1] = f2tf(qr1[kk * 8 + t]);
            Qf[kk][2] = f2tf(qr0[kk * 8 + t + 4]);
            Qf[kk][3] = f2tf(qr1[kk * 8 + t + 4]);
        }
    }
    __syncthreads();

    // global-key score for this thread's two rows (quad-collective dot)
    float p0 = 0.f, p1 = 0.f;
#pragma unroll
    for (int kk = 0; kk < 8; kk++) {
        p0 += __uint_as_float(Qf[kk][0]) * k0s[kk*8 + t] + __uint_as_float(Qf[kk][2]) * k0s[kk*8 + t + 4];
        p1 += __uint_as_float(Qf[kk][1]) * k0s[kk*8 + t] + __uint_as_float(Qf[kk][3]) * k0s[kk*8 + t + 4];
    }
    p0 += __shfl_xor_sync(0xffffffffu, p0, 1); p0 += __shfl_xor_sync(0xffffffffu, p0, 2);
    p1 += __shfl_xor_sync(0xffffffffu, p1, 1); p1 += __shfl_xor_sync(0xffffffffu, p1, 2);

    const bool m0set = mask[(size_t)b * S_] != 0;
    float m0 = m0set ? p0 : -1e30f;
    float m1 = m0set ? p1 : -1e30f;
    float l0 = m0set ? 1.f : 0.f;
    float l1 = l0;
    float acc[8][4];
#pragma unroll
    for (int nt = 0; nt < 8; nt++) {
        float va = m0set ? v0s[nt*8 + 2*t]     : 0.f;
        float vb = m0set ? v0s[nt*8 + 2*t + 1] : 0.f;
        acc[nt][0] = va; acc[nt][1] = vb; acc[nt][2] = va; acc[nt][3] = vb;
    }

    const int base = c * W_ - W_;
    const int q0r = wq + g, q1r = q0r + 8;
    const uint32_t* Ku = (const uint32_t*)Ks;
    const uint32_t* Vu = (const uint32_t*)Vs;

    for (int tile = 0; tile < 6; tile++) {
        __syncthreads();
#pragma unroll
        for (int e = 0; e < 4; e++) {
            int id = tid + e * 256;
            int r = id >> 4, c4 = (id & 15) * 4;
            int p = base + tile * 64 + r;
            float4 kv = make_float4(0.f,0.f,0.f,0.f), vv = kv;
            if (p >= 0 && p < S_) {
                size_t off = hb + (size_t)p * D_ + c4;
                kv = *(const float4*)(k + off);
                vv = *(const float4*)(v + off);
            }
            uint32_t* kd = (uint32_t*)&Ks[r * 68 + c4];
            kd[0] = f2tf(kv.x); kd[1] = f2tf(kv.y); kd[2] = f2tf(kv.z); kd[3] = f2tf(kv.w);
            uint32_t* vd = (uint32_t*)&Vs[r * 72 + c4];
            vd[0] = f2tf(vv.x); vd[1] = f2tf(vv.y); vd[2] = f2tf(vv.z); vd[3] = f2tf(vv.w);
        }
        if (tid < 64) {
            int p = base + tile * 64 + tid;
            vld[tid] = (p >= 0 && p < S_) ? (mask[(size_t)b * S_ + p] != 0) : 0;
        }
        __syncthreads();

        // QK^T: sc[nt][0..3]
        float sc[8][4];
#pragma unroll
        for (int nt = 0; nt < 8; nt++) { sc[nt][0]=0.f; sc[nt][1]=0.f; sc[nt][2]=0.f; sc[nt][3]=0.f; }
#pragma unroll
        for (int kk = 0; kk < 8; kk++) {
#pragma unroll
            for (int nt = 0; nt < 8; nt++) {
                unsigned bf[2];
                bf[0] = Ku[(nt*8 + g) * 68 + kk*8 + t];
                bf[1] = Ku[(nt*8 + g) * 68 + kk*8 + t + 4];
                mma_tf32(sc[nt], Qf[kk], bf);
            }
        }

        // mask + row max
        float tm0 = -1e30f, tm1 = -1e30f;
#pragma unroll
        for (int nt = 0; nt < 8; nt++) {
            int j0 = tile*64 + nt*8 + 2*t, j1 = j0 + 1;
            bool ok00 = (j0 >= q0r) && (j0 <= q0r + 2*W_) && vld[nt*8 + 2*t];
            bool ok01 = (j1 >= q0r) && (j1 <= q0r + 2*W_) && vld[nt*8 + 2*t + 1];
            bool ok10 = (j0 >= q1r) && (j0 <= q1r + 2*W_) && vld[nt*8 + 2*t];
            bool ok11 = (j1 >= q1r) && (j1 <= q1r + 2*W_) && vld[nt*8 + 2*t + 1];
            sc[nt][0] = ok00 ? sc[nt][0] : -1e30f;
            sc[nt][1] = ok01 ? sc[nt][1] : -1e30f;
            sc[nt][2] = ok10 ? sc[nt][2] : -1e30f;
            sc[nt][3] = ok11 ? sc[nt][3] : -1e30f;
            tm0 = fmaxf(tm0, fmaxf(sc[nt][0], sc[nt][1]));
            tm1 = fmaxf(tm1, fmaxf(sc[nt][2], sc[nt][3]));
        }
        tm0 = fmaxf(tm0, __shfl_xor_sync(0xffffffffu, tm0, 1));
        tm0 = fmaxf(tm0, __shfl_xor_sync(0xffffffffu, tm0, 2));
        tm1 = fmaxf(tm1, __shfl_xor_sync(0xffffffffu, tm1, 1));
        tm1 = fmaxf(tm1, __shfl_xor_sync(0xffffffffu, tm1, 2));

        float nm0 = fmaxf(m0, tm0), nm1 = fmaxf(m1, tm1);
        float cr0 = __expf(m0 - nm0), cr1 = __expf(m1 - nm1);
        m0 = nm0; m1 = nm1; l0 *= cr0; l1 *= cr1;

        float ps0 = 0.f, ps1 = 0.f;
#pragma unroll
        for (int nt = 0; nt < 8; nt++) {
            sc[nt][0] = (sc[nt][0] > -1e29f) ? __expf(sc[nt][0] - m0) : 0.f;
            sc[nt][1] = (sc[nt][1] > -1e29f) ? __expf(sc[nt][1] - m0) : 0.f;
            sc[nt][2] = (sc[nt][2] > -1e29f) ? __expf(sc[nt][2] - m1) : 0.f;
            sc[nt][3] = (sc[nt][3] > -1e29f) ? __expf(sc[nt][3] - m1) : 0.f;
            ps0 += sc[nt][0] + sc[nt][1];
            ps1 += sc[nt][2] + sc[nt][3];
            acc[nt][0] *= cr0; acc[nt][1] *= cr0; acc[nt][2] *= cr1; acc[nt][3] *= cr1;
        }
        ps0 += __shfl_xor_sync(0xffffffffu, ps0, 1); ps0 += __shfl_xor_sync(0xffffffffu, ps0, 2);
        ps1 += __shfl_xor_sync(0xffffffffu, ps1, 1); ps1 += __shfl_xor_sync(0xffffffffu, ps1, 2);
        l0 += ps0; l1 += ps1;

        // PV: C-frag -> A-frag via quad shuffles, then mma
        const int src0 = (lane & ~3) | (t >> 1);
        const int src1 = src0 + 2;
        const bool odd = t & 1;
#pragma unroll
        for (int kk = 0; kk < 8; kk++) {
            float x0 = __shfl_sync(0xffffffffu, sc[kk][0], src0);
            float x1 = __shfl_sync(0xffffffffu, sc[kk][1], src0);
            float x2 = __shfl_sync(0xffffffffu, sc[kk][2], src0);
            float x3 = __shfl_sync(0xffffffffu, sc[kk][3], src0);
            float y0 = __shfl_sync(0xffffffffu, sc[kk][0], src1);
            float y1 = __shfl_sync(0xffffffffu, sc[kk][1], src1);
            float y2 = __shfl_sync(0xffffffffu, sc[kk][2], src1);
            float y3 = __shfl_sync(0xffffffffu, sc[kk][3], src1);
            unsigned af[4];
            af[0] = f2tf(odd ? x1 : x0);
            af[1] = f2tf(odd ? x3 : x2);
            af[2] = f2tf(odd ? y1 : y0);
            af[3] = f2tf(odd ? y3 : y2);
#pragma unroll
            for (int nt = 0; nt < 8; nt++) {
                unsigned bf[2];
                bf[0] = Vu[(kk*8 + t) * 72 + nt*8 + g];
                bf[1] = Vu[(kk*8 + t + 4) * 72 + nt*8 + g];
                mma_tf32(acc[nt], af, bf);
            }
        }
    }

    float inv0 = 1.f / l0, inv1 = 1.f / l1;
    float* or0 = out + hb + (size_t)(c * W_ + wq + g) * D_;
    float* or1 = or0 + 8 * D_;
#pragma unroll
    for (int nt = 0; nt < 8; nt++) {
        *(float2*)(or0 + nt*8 + 2*t) = make_float2(acc[nt][0] * inv0, acc[nt][1] * inv0);
        *(float2*)(or1 + nt*8 + 2*t) = make_float2(acc[nt][2] * inv1, acc[nt][3] * inv1);
    }
}

// ---------------- global-token attention -> overwrite out row 0 ----------------
__global__ void __launch_bounds__(256) gattn_kernel(
    const float* __restrict__ qg, const float* __restrict__ kg,
    const float* __restrict__ vg, const int* __restrict__ mask,
    float* __restrict__ out) {
    const int hh = blockIdx.x, b = blockIdx.y;
    const int tid = threadIdx.x;
    __shared__ float sc[S_];
    __shared__ float qs[HD_];
    __shared__ float r1[8];
    __shared__ float stat[2];
    __shared__ float accb[4][HD_];
    if (tid < HD_) qs[tid] = qg[b * D_ + hh * HD_ + tid];
    __syncthreads();
    float lmax = -3.4e38f;
    for (int s = tid; s < S_; s += 256) {
        const float4* kr = (const float4*)(kg + ((size_t)b * S_ + s) * D_ + hh * HD_);
        float dot = 0.f;
#pragma unroll
        for (int i = 0; i < 16; i++) {
            float4 k4 = kr[i];
            dot = fmaf(qs[i*4], k4.x, dot);   dot = fmaf(qs[i*4+1], k4.y, dot);
            dot = fmaf(qs[i*4+2], k4.z, dot); dot = fmaf(qs[i*4+3], k4.w, dot);
        }
        if (mask[(size_t)b * S_ + s] == 0) dot = -1e9f;
        sc[s] = dot;
        lmax = fmaxf(lmax, dot);
    }
    {
        int lane = tid & 31, wid = tid >> 5;
#pragma unroll
        for (int o = 16; o > 0; o >>= 1) lmax = fmaxf(lmax, __shfl_down_sync(0xffffffffu, lmax, o));
        if (lane == 0) r1[wid] = lmax;
        __syncthreads();
        if (tid == 0) {
            float m2 = r1[0];
            for (int i = 1; i < 8; i++) m2 = fmaxf(m2, r1[i]);
            stat[0] = m2;
        }
        __syncthreads();
    }
    float gmax = stat[0];
    float lsum = 0.f;
    for (int s = tid; s < S_; s += 256) {
        float e = __expf(sc[s] - gmax);
        sc[s] = e;
        lsum += e;
    }
    {
        int lane = tid & 31, wid = tid >> 5;
#pragma unroll
        for (int o = 16; o > 0; o >>= 1) lsum += __shfl_down_sync(0xffffffffu, lsum, o);
        if (lane == 0) r1[wid] = lsum;
        __syncthreads();
        if (tid == 0) {
            float s2 = 0.f;
            for (int i = 0; i < 8; i++) s2 += r1[i];
            stat[1] = s2;
        }
        __syncthreads();
    }
    float inv = 1.f / stat[1];
    int d = tid & 63, part = tid >> 6;
    float a = 0.f;
    for (int s = part; s < S_; s += 4)
        a = fmaf(sc[s], vg[((size_t)b * S_ + s) * D_ + hh * HD_ + d], a);
    accb[part][d] = a;
    __syncthreads();
    if (tid < HD_)
        out[(size_t)b * S_ * D_ + hh * HD_ + tid] =
            (accb[0][tid] + accb[1][tid] + accb[2][tid] + accb[3][tid]) * inv;
}

// ---------------- classifier head ----------------
__global__ void cls_kernel(const float* __restrict__ h, const float* __restrict__ Wcls,
                           const float* __restrict__ bcls, const int* __restrict__ mask,
                           float* __restrict__ out) {
    int w = threadIdx.x >> 5, lane = threadIdx.x & 31;
    int b = w & 1, j = w >> 1;
    float s = 0.f;
    for (int kk = lane; kk < D_; kk += 32)
        s = fmaf(h[(size_t)b * S_ * D_ + kk], Wcls[kk * 3 + j], s);
#pragma unroll
    for (int o = 16; o > 0; o >>= 1) s += __shfl_down_sync(0xffffffffu, s, o);
    if (lane == 0) out[j * 2 + b] = 1.f / (1.f + expf(-(s + bcls[j])));
    if (threadIdx.x < 2) out[6 + threadIdx.x] = (float)mask[(size_t)threadIdx.x * S_];
}

// ---------------- launch ----------------
extern "C" void kernel_launch(void* const* d_in, const int* in_sizes, int n_in,
                              void* d_out, int out_size) {
    const int*   src  = (const int*)d_in[0];
    const int*   mask = (const int*)d_in[1];
    const float* etok = (const float*)d_in[3];
    const float* epos = (const float*)d_in[4];
    const float* elns = (const float*)d_in[5];
    const float* elnb = (const float*)d_in[6];
    const float* Wq   = (const float*)d_in[7];   const float* bq_p  = (const float*)d_in[8];
    const float* Wk   = (const float*)d_in[9];   const float* bk_p  = (const float*)d_in[10];
    const float* Wv   = (const float*)d_in[11];  const float* bv_p  = (const float*)d_in[12];
    const float* Wo   = (const float*)d_in[13];  const float* bo_p  = (const float*)d_in[14];
    const float* Wqg  = (const float*)d_in[15];  const float* bqg_p = (const float*)d_in[16];
    const float* Wkg  = (const float*)d_in[17];  const float* bkg_p = (const float*)d_in[18];
    const float* Wvg  = (const float*)d_in[19];  const float* bvg_p = (const float*)d_in[20];
    const float* ln1s = (const float*)d_in[21];  const float* ln1b  = (const float*)d_in[22];
    const float* W1   = (const float*)d_in[23];  const float* b1_p  = (const float*)d_in[24];
    const float* W2   = (const float*)d_in[25];  const float* b2_p  = (const float*)d_in[26];
    const float* ln2s = (const float*)d_in[27];  const float* ln2b  = (const float*)d_in[28];
    const float* Wcls = (const float*)d_in[29];  const float* bcls  = (const float*)d_in[30];
    float* out = (float*)d_out;

    float *ph, *pq, *pk, *pv, *pkg, *pvg, *pa, *pt, *pf, *pqg;
    cudaGetSymbolAddress((void**)&ph,  g_h);
    cudaGetSymbolAddress((void**)&pq,  g_q);
    cudaGetSymbolAddress((void**)&pk,  g_k);
    cudaGetSymbolAddress((void**)&pv,  g_v);
    cudaGetSymbolAddress((void**)&pkg, g_kg);
    cudaGetSymbolAddress((void**)&pvg, g_vg);
    cudaGetSymbolAddress((void**)&pa,  g_a);
    cudaGetSymbolAddress((void**)&pt,  g_t);
    cudaGetSymbolAddress((void**)&pf,  g_ff);
    cudaGetSymbolAddress((void**)&pqg, g_qg);

    const int M = B_ * S_;   // 4096

    embed_ln_kernel<<<M, 256>>>(src, etok, epos, elns, elnb, ph);

    for (int l = 0; l < L_; l++) {
        size_t wo  = (size_t)l * D_ * D_;
        size_t bof = (size_t)l * D_;

        ProjParams pp;
        pp.W[0] = Wq  + wo; pp.b[0] = bq_p  + bof; pp.o[0] = pq;  pp.alpha[0] = 0.125f;
        pp.W[1] = Wk  + wo; pp.b[1] = bk_p  + bof; pp.o[1] = pk;  pp.alpha[1] = 1.f;
        pp.W[2] = Wv  + wo; pp.b[2] = bv_p  + bof; pp.o[2] = pv;  pp.alpha[2] = 1.f;
        pp.W[3] = Wkg + wo; pp.b[3] = bkg_p + bof; pp.o[3] = pkg; pp.alpha[3] = 1.f;
        pp.W[4] = Wvg + wo; pp.b[4] = bvg_p + bof; pp.o[4] = pvg; pp.alpha[4] = 1.f;
        proj_gemm_kernel<<<dim3(D_ / 128, M / 128, 5), 128>>>(ph, pp, M, D_, D_);

        qg_kernel<<<dim3(B_, 3), 256>>>(ph, Wqg + wo, bqg_p + bof, pqg);
        attn_kernel<<<dim3(NC_, H_, B_), 256>>>(pq, pk, pv, mask, pa);
        gattn_kernel<<<dim3(H_, B_), 256>>>(pqg, pkg, pvg, mask, pa);

        tgemm_kernel<0><<<dim3(D_ / 128, M / 128), 128>>>(pa, Wo + wo, bo_p + bof, pt, M, D_, D_, 1.f);
        add_ln_kernel<<<M, 256>>>(ph, pt, ln1s + bof, ln1b + bof);
        tgemm_kernel<1><<<dim3(FF_ / 128, M / 128), 128>>>(ph, W1 + (size_t)l * D_ * FF_,
                                                           b1_p + (size_t)l * FF_, pf, M, FF_, D_, 1.f);
        tgemm_kernel<0><<<dim3(D_ / 128, M / 128), 128>>>(pf, W2 + (size_t)l * FF_ * D_,
                                                          b2_p + bof, pt, M, D_, FF_, 1.f);
        add_ln_kernel<<<M, 256>>>(ph, pt, ln2s + bof, ln2b + bof);
    }

    cls_kernel<<<1, 192>>>(ph, Wcls, bcls, mask, out);
}